// round 4
// baseline (speedup 1.0000x reference)
#include <cuda_runtime.h>

// Problem-fixed dims (from setup_inputs): N=100000, E=1600000, IN=128, H=64, OUT=32
#define MAXN 100000
#define MAXE 1600000
#define IN_DIM 128
#define H_DIM 64
#define OUT_DIM 32

// ---------------- scratch (device globals; no allocation allowed) ------------
__device__ int   g_is64;                    // 1 if edge_index is int64, 0 if int32
__device__ __align__(16) float g_deg [MAXN];
__device__ __align__(16) float g_dinv[MAXN];
__device__ __align__(16) int   g_src [MAXE];
__device__ __align__(16) int   g_dst [MAXE];
__device__ __align__(16) float g_norm[MAXE];
__device__ __align__(16) float g_Z1[(size_t)MAXN * H_DIM]; // x@W1
__device__ __align__(16) float g_h [(size_t)MAXN * H_DIM]; // conv1 out (pre-relu)
__device__ __align__(16) float g_Z2[(size_t)MAXN * H_DIM]; // relu(h)@[Wmu|Wlog]
__device__ __align__(16) float g_out[(size_t)2 * MAXN * OUT_DIM]; // [mu; log] staging

// ---------------- dtype probe ------------------------------------------------
// int64 little-endian values < 2^31 have all-zero odd 32-bit words.
// int32 real indices make odd words nonzero with overwhelming probability.
__global__ void k_probe(const int* __restrict__ raw, int total_i32) {
    __shared__ int nz;
    if (threadIdx.x == 0) nz = 0;
    __syncthreads();
    int K = 2048;  // inspect first 1024 odd words
    if (K > total_i32) K = total_i32;
    int cnt = 0;
    for (int i = 2 * threadIdx.x + 1; i < K; i += 2 * blockDim.x)
        if (raw[i] != 0) cnt++;
    if (cnt) atomicAdd(&nz, cnt);
    __syncthreads();
    if (threadIdx.x == 0) g_is64 = (nz == 0) ? 1 : 0;
}

// ---------------- extract + clamp edges --------------------------------------
__global__ void k_extract(const int* __restrict__ raw, int E, int n) {
    int i = blockIdx.x * blockDim.x + threadIdx.x;
    if (i >= E) return;
    int s, d;
    if (g_is64) {
        const long long* e64 = (const long long*)raw;
        s = (int)e64[i];
        d = (int)e64[(size_t)E + i];
    } else {
        s = raw[i];
        d = raw[E + i];
    }
    if ((unsigned)s >= (unsigned)n) s = 0;  // safety clamp
    if ((unsigned)d >= (unsigned)n) d = 0;
    g_src[i] = s;
    g_dst[i] = d;
}

// ---------------- norm pipeline ---------------------------------------------
__global__ void k_init_deg(int n) {
    int i = blockIdx.x * blockDim.x + threadIdx.x;
    if (i < n) g_deg[i] = 1.0f;  // self-loop
}

__global__ void k_deg(int E) {
    int i = blockIdx.x * blockDim.x + threadIdx.x;
    if (i < E) atomicAdd(&g_deg[g_dst[i]], 1.0f);
}

__global__ void k_dinv(int n) {
    int i = blockIdx.x * blockDim.x + threadIdx.x;
    if (i < n) g_dinv[i] = rsqrtf(g_deg[i]);
}

__global__ void k_norm(int E) {
    int i = blockIdx.x * blockDim.x + threadIdx.x;
    if (i < E) g_norm[i] = g_dinv[g_src[i]] * g_dinv[g_dst[i]];
}

// ---------------- GEMM1: Z1 = x @ W1   [N,128]x[128,64] ---------------------
__global__ __launch_bounds__(256) void k_gemm1(const float* __restrict__ x,
                                               const float* __restrict__ W1, int n) {
    __shared__ float Bs[IN_DIM * H_DIM];  // 32 KB
    int tid = threadIdx.x;
    for (int i = tid; i < IN_DIM * H_DIM; i += 256) Bs[i] = W1[i];
    __syncthreads();
    int row = blockIdx.x * 256 + tid;
    if (row >= n) return;

    float4 acc[16];
#pragma unroll
    for (int i = 0; i < 16; i++) acc[i] = make_float4(0.f, 0.f, 0.f, 0.f);

    const float4* arow = (const float4*)(x + (size_t)row * IN_DIM);
#pragma unroll 2
    for (int k4 = 0; k4 < IN_DIM / 4; k4++) {
        float4 a4 = arow[k4];
        float av[4] = {a4.x, a4.y, a4.z, a4.w};
#pragma unroll
        for (int kk = 0; kk < 4; kk++) {
            float a = av[kk];
            const float4* br = (const float4*)(Bs + (k4 * 4 + kk) * H_DIM);
#pragma unroll
            for (int c = 0; c < 16; c++) {
                float4 b = br[c];
                acc[c].x = fmaf(a, b.x, acc[c].x);
                acc[c].y = fmaf(a, b.y, acc[c].y);
                acc[c].z = fmaf(a, b.z, acc[c].z);
                acc[c].w = fmaf(a, b.w, acc[c].w);
            }
        }
    }
    float4* crow = (float4*)(g_Z1 + (size_t)row * H_DIM);
#pragma unroll
    for (int c = 0; c < 16; c++) crow[c] = acc[c];
}

// ---------------- init h = b1 + Z1 * dinv^2 (self-loop folded in) ------------
__global__ void k_init_h(const float* __restrict__ b1, int n) {
    int i = blockIdx.x * blockDim.x + threadIdx.x;
    if (i >= n * 16) return;
    int row = i >> 4, j = i & 15;
    float s = g_dinv[row];
    float s2 = s * s;
    float4 z = ((const float4*)g_Z1)[(size_t)row * 16 + j];
    float4 b = ((const float4*)b1)[j];
    float4 o = make_float4(fmaf(z.x, s2, b.x), fmaf(z.y, s2, b.y),
                           fmaf(z.z, s2, b.z), fmaf(z.w, s2, b.w));
    ((float4*)g_h)[(size_t)row * 16 + j] = o;
}

// ---------------- edge aggregation into h ------------------------------------
__global__ void k_agg1(int E) {
    int i = blockIdx.x * blockDim.x + threadIdx.x;
    if (i >= E * 16) return;
    int e = i >> 4, j = i & 15;
    int s = g_src[e], d = g_dst[e];
    float w = g_norm[e];
    float4 v = ((const float4*)g_Z1)[(size_t)s * 16 + j];
    float* p = g_h + (size_t)d * H_DIM + j * 4;
    atomicAdd(p + 0, v.x * w);   // return unused -> RED.E.ADD.F32 (device global)
    atomicAdd(p + 1, v.y * w);
    atomicAdd(p + 2, v.z * w);
    atomicAdd(p + 3, v.w * w);
}

// ---------------- GEMM2: Z2 = relu(h) @ [Wmu|Wlog]  [N,64]x[64,64] ----------
__global__ __launch_bounds__(256) void k_gemm2(const float* __restrict__ Wmu,
                                               const float* __restrict__ Wlog, int n) {
    __shared__ float Bs[H_DIM * 64];  // 16 KB: cols 0..31 = Wmu, 32..63 = Wlog
    int tid = threadIdx.x;
    for (int i = tid; i < H_DIM * OUT_DIM; i += 256) {
        int k = i / OUT_DIM, c = i % OUT_DIM;
        Bs[k * 64 + c]      = Wmu[i];
        Bs[k * 64 + 32 + c] = Wlog[i];
    }
    __syncthreads();
    int row = blockIdx.x * 256 + tid;
    if (row >= n) return;

    float4 acc[16];
#pragma unroll
    for (int i = 0; i < 16; i++) acc[i] = make_float4(0.f, 0.f, 0.f, 0.f);

    const float4* arow = (const float4*)(g_h + (size_t)row * H_DIM);
#pragma unroll 2
    for (int k4 = 0; k4 < H_DIM / 4; k4++) {
        float4 a4 = arow[k4];
        a4.x = fmaxf(a4.x, 0.f);  // relu(h) applied at read
        a4.y = fmaxf(a4.y, 0.f);
        a4.z = fmaxf(a4.z, 0.f);
        a4.w = fmaxf(a4.w, 0.f);
        float av[4] = {a4.x, a4.y, a4.z, a4.w};
#pragma unroll
        for (int kk = 0; kk < 4; kk++) {
            float a = av[kk];
            const float4* br = (const float4*)(Bs + (k4 * 4 + kk) * 64);
#pragma unroll
            for (int c = 0; c < 16; c++) {
                float4 b = br[c];
                acc[c].x = fmaf(a, b.x, acc[c].x);
                acc[c].y = fmaf(a, b.y, acc[c].y);
                acc[c].z = fmaf(a, b.z, acc[c].z);
                acc[c].w = fmaf(a, b.w, acc[c].w);
            }
        }
    }
    float4* crow = (float4*)(g_Z2 + (size_t)row * H_DIM);
#pragma unroll
    for (int c = 0; c < 16; c++) crow[c] = acc[c];
}

// ---------------- init g_out = bias + Z2 * dinv^2 ----------------------------
// g_out layout: mu rows [0, N), log rows at offset N*OUT_DIM.
__global__ void k_init_out(const float* __restrict__ bmu, const float* __restrict__ blog,
                           int n) {
    int i = blockIdx.x * blockDim.x + threadIdx.x;
    if (i >= n * 16) return;
    int row = i >> 4, j = i & 15;
    float s = g_dinv[row];
    float s2 = s * s;
    float4 z = ((const float4*)g_Z2)[(size_t)row * 16 + j];
    int jj = j & 7;
    const float* bp = (j < 8) ? bmu : blog;
    float4 b = ((const float4*)bp)[jj];
    float4 o = make_float4(fmaf(z.x, s2, b.x), fmaf(z.y, s2, b.y),
                           fmaf(z.z, s2, b.z), fmaf(z.w, s2, b.w));
    size_t base = (j < 8) ? 0 : (size_t)n * OUT_DIM;
    float* op = g_out + base + (size_t)row * OUT_DIM + jj * 4;
    *(float4*)op = o;
}

// ---------------- edge aggregation into g_out --------------------------------
__global__ void k_agg2(int n, int E) {
    int i = blockIdx.x * blockDim.x + threadIdx.x;
    if (i >= E * 16) return;
    int e = i >> 4, j = i & 15;
    int s = g_src[e], d = g_dst[e];
    float w = g_norm[e];
    float4 v = ((const float4*)g_Z2)[(size_t)s * 16 + j];
    int jj = j & 7;
    size_t base = (j < 8) ? 0 : (size_t)n * OUT_DIM;
    float* p = g_out + base + (size_t)d * OUT_DIM + jj * 4;
    atomicAdd(p + 0, v.x * w);   // device-global scratch only
    atomicAdd(p + 1, v.y * w);
    atomicAdd(p + 2, v.z * w);
    atomicAdd(p + 3, v.w * w);
}

// ---------------- final copy: g_out -> d_out (plain stores only) -------------
__global__ void k_copy_out(float* __restrict__ out, int total4) {
    int i = blockIdx.x * blockDim.x + threadIdx.x;
    if (i < total4) ((float4*)out)[i] = ((const float4*)g_out)[i];
}

// ---------------- launch -----------------------------------------------------
extern "C" void kernel_launch(void* const* d_in, const int* in_sizes, int n_in,
                              void* d_out, int out_size) {
    const float* x    = (const float*)d_in[0];
    const int*   eraw = (const int*)d_in[1];     // int32 OR int64; probed on device
    const float* W1   = (const float*)d_in[2];
    const float* b1   = (const float*)d_in[3];
    const float* Wmu  = (const float*)d_in[4];
    const float* bmu  = (const float*)d_in[5];
    const float* Wlog = (const float*)d_in[6];
    const float* blog = (const float*)d_in[7];

    int N = in_sizes[0] / IN_DIM;   // 100000
    int E = in_sizes[1] / 2;        // 1600000 (element count is dtype-agnostic)
    if (N > MAXN) N = MAXN;
    if (E > MAXE) E = MAXE;

    const int T = 256;
    int gN   = (N + T - 1) / T;
    int gE   = (E + T - 1) / T;
    int gN16 = (N * 16 + T - 1) / T;
    int gE16 = (E * 16 + T - 1) / T;

    // dtype probe + edge extraction + norm pipeline
    k_probe<<<1, 256>>>(eraw, 2 * E);
    k_extract<<<gE, T>>>(eraw, E, N);
    k_init_deg<<<gN, T>>>(N);
    k_deg<<<gE, T>>>(E);
    k_dinv<<<gN, T>>>(N);
    k_norm<<<gE, T>>>(E);

    // layer 1
    k_gemm1<<<gN, T>>>(x, W1, N);
    k_init_h<<<gN16, T>>>(b1, N);
    k_agg1<<<gE16, T>>>(E);

    // layer 2 (mu and log fused)
    k_gemm2<<<gN, T>>>(Wmu, Wlog, N);
    k_init_out<<<gN16, T>>>(bmu, blog, N);
    k_agg2<<<gE16, T>>>(N, E);

    // stage -> real output (no atomics on harness memory)
    int total4 = (2 * N * OUT_DIM) / 4;
    k_copy_out<<<(total4 + T - 1) / T, T>>>((float*)d_out, total4);
}

// round 7
// speedup vs baseline: 1.3802x; 1.3802x over previous
#include <cuda_runtime.h>

// Problem-fixed dims: N=100000, E=1600000, IN=128, H=64, OUT=32
#define MAXN 100000
#define MAXE 1600000
#define IN_DIM 128
#define H_DIM 64
#define OUT_DIM 32

// ---------------- scratch (device globals; no allocation allowed) ------------
__device__ int   g_is64;                       // edge_index dtype flag
__device__ __align__(16) int   g_src [MAXE];
__device__ __align__(16) int   g_dst [MAXE];
__device__ __align__(16) int   g_cnt [MAXN];   // in-degree (excl self-loop)
__device__ __align__(16) int   g_row [MAXN + 1];
__device__ __align__(16) int   g_cur [MAXN];
__device__ __align__(16) float g_dinv[MAXN];
__device__ __align__(16) int2  g_csr [MAXE];   // (src, norm-bits) sorted by dst
__device__ __align__(16) float g_Z1[(size_t)MAXN * H_DIM]; // x@W1
__device__ __align__(16) float g_h [(size_t)MAXN * H_DIM]; // conv1 out (pre-relu)
__device__ __align__(16) float g_Z2[(size_t)MAXN * H_DIM]; // relu(h)@[Wmu|Wlog]

// ---------------- dtype probe ------------------------------------------------
__global__ void k_probe(const int* __restrict__ raw, int total_i32) {
    __shared__ int nz;
    if (threadIdx.x == 0) nz = 0;
    __syncthreads();
    int K = 2048;
    if (K > total_i32) K = total_i32;
    int cnt = 0;
    for (int i = 2 * threadIdx.x + 1; i < K; i += 2 * blockDim.x)
        if (raw[i] != 0) cnt++;
    if (cnt) atomicAdd(&nz, cnt);
    __syncthreads();
    if (threadIdx.x == 0) g_is64 = (nz == 0) ? 1 : 0;
}

// ---------------- extract + clamp edges, zero counts -------------------------
__global__ void k_extract(const int* __restrict__ raw, int E, int n) {
    int i = blockIdx.x * blockDim.x + threadIdx.x;
    if (i < n) g_cnt[i] = 0;
    if (i >= E) return;
    int s, d;
    if (g_is64) {
        const long long* e64 = (const long long*)raw;
        s = (int)e64[i];
        d = (int)e64[(size_t)E + i];
    } else {
        s = raw[i];
        d = raw[E + i];
    }
    if ((unsigned)s >= (unsigned)n) s = 0;
    if ((unsigned)d >= (unsigned)n) d = 0;
    g_src[i] = s;
    g_dst[i] = d;
}

__global__ void k_count(int E) {
    int i = blockIdx.x * blockDim.x + threadIdx.x;
    if (i < E) atomicAdd(&g_cnt[g_dst[i]], 1);
}

// ---------------- single-block exclusive scan over counts --------------------
__global__ __launch_bounds__(1024) void k_scan(int n) {
    __shared__ int ssum[1024];
    int t = threadIdx.x;
    int chunk = (n + 1023) >> 10;
    int lo = t * chunk;
    int hi = lo + chunk; if (hi > n) hi = n; if (lo > n) lo = n;
    int s = 0;
    for (int i = lo; i < hi; i++) s += g_cnt[i];
    ssum[t] = s;
    __syncthreads();
    for (int off = 1; off < 1024; off <<= 1) {
        int v = (t >= off) ? ssum[t - off] : 0;
        __syncthreads();
        ssum[t] += v;
        __syncthreads();
    }
    int base = (t == 0) ? 0 : ssum[t - 1];
    for (int i = lo; i < hi; i++) {
        int c = g_cnt[i];
        g_row[i] = base;
        g_cur[i] = base;
        base += c;
    }
    if (t == 0) g_row[n] = ssum[1023];
}

__global__ void k_dinv(int n) {
    int i = blockIdx.x * blockDim.x + threadIdx.x;
    if (i < n) g_dinv[i] = rsqrtf(1.0f + (float)g_cnt[i]);  // +1 self-loop
}

// ---------------- scatter into CSR (norm computed here) ----------------------
__global__ void k_scatter(int E) {
    int i = blockIdx.x * blockDim.x + threadIdx.x;
    if (i >= E) return;
    int s = g_src[i], d = g_dst[i];
    float w = g_dinv[s] * g_dinv[d];
    int pos = atomicAdd(&g_cur[d], 1);
    g_csr[pos] = make_int2(s, __float_as_int(w));
}

// ---------------- GEMM1: Z1 = x @ W1   [N,128]x[128,64] ---------------------
__global__ __launch_bounds__(256) void k_gemm1(const float* __restrict__ x,
                                               const float* __restrict__ W1, int n) {
    __shared__ float Bs[IN_DIM * H_DIM];  // 32 KB
    int tid = threadIdx.x;
    for (int i = tid; i < IN_DIM * H_DIM; i += 256) Bs[i] = W1[i];
    __syncthreads();
    int row = blockIdx.x * 256 + tid;
    if (row >= n) return;

    float4 acc[16];
#pragma unroll
    for (int i = 0; i < 16; i++) acc[i] = make_float4(0.f, 0.f, 0.f, 0.f);

    const float4* arow = (const float4*)(x + (size_t)row * IN_DIM);
#pragma unroll 2
    for (int k4 = 0; k4 < IN_DIM / 4; k4++) {
        float4 a4 = arow[k4];
        float av[4] = {a4.x, a4.y, a4.z, a4.w};
#pragma unroll
        for (int kk = 0; kk < 4; kk++) {
            float a = av[kk];
            const float4* br = (const float4*)(Bs + (k4 * 4 + kk) * H_DIM);
#pragma unroll
            for (int c = 0; c < 16; c++) {
                float4 b = br[c];
                acc[c].x = fmaf(a, b.x, acc[c].x);
                acc[c].y = fmaf(a, b.y, acc[c].y);
                acc[c].z = fmaf(a, b.z, acc[c].z);
                acc[c].w = fmaf(a, b.w, acc[c].w);
            }
        }
    }
    float4* crow = (float4*)(g_Z1 + (size_t)row * H_DIM);
#pragma unroll
    for (int c = 0; c < 16; c++) crow[c] = acc[c];
}

// ---------------- CSR aggregation 1: warp per dst node -----------------------
// h[v] = b1 + dinv[v]^2 * Z1[v] + sum_e w_e * Z1[src_e]    (plain stores)
__global__ __launch_bounds__(256) void k_agg1_csr(const float* __restrict__ b1, int n) {
    int warp = (blockIdx.x * 256 + threadIdx.x) >> 5;
    int lane = threadIdx.x & 31;
    if (warp >= n) return;
    int rs = g_row[warp], re = g_row[warp + 1];
    float dv = g_dinv[warp];
    float s2 = dv * dv;
    const float2* zb = (const float2*)g_Z1;
    float2 zs = zb[(size_t)warp * 32 + lane];
    float2 b  = ((const float2*)b1)[lane];
    float2 acc = make_float2(fmaf(zs.x, s2, b.x), fmaf(zs.y, s2, b.y));
    for (int e = rs; e < re; e++) {
        int2 ed = g_csr[e];
        float w = __int_as_float(ed.y);
        float2 z = zb[(size_t)ed.x * 32 + lane];
        acc.x = fmaf(w, z.x, acc.x);
        acc.y = fmaf(w, z.y, acc.y);
    }
    ((float2*)g_h)[(size_t)warp * 32 + lane] = acc;
}

// ---------------- GEMM2: Z2 = relu(h) @ [Wmu|Wlog]  [N,64]x[64,64] ----------
__global__ __launch_bounds__(256) void k_gemm2(const float* __restrict__ Wmu,
                                               const float* __restrict__ Wlog, int n) {
    __shared__ float Bs[H_DIM * 64];  // cols 0..31 = Wmu, 32..63 = Wlog
    int tid = threadIdx.x;
    for (int i = tid; i < H_DIM * OUT_DIM; i += 256) {
        int k = i / OUT_DIM, c = i % OUT_DIM;
        Bs[k * 64 + c]      = Wmu[i];
        Bs[k * 64 + 32 + c] = Wlog[i];
    }
    __syncthreads();
    int row = blockIdx.x * 256 + tid;
    if (row >= n) return;

    float4 acc[16];
#pragma unroll
    for (int i = 0; i < 16; i++) acc[i] = make_float4(0.f, 0.f, 0.f, 0.f);

    const float4* arow = (const float4*)(g_h + (size_t)row * H_DIM);
#pragma unroll 2
    for (int k4 = 0; k4 < H_DIM / 4; k4++) {
        float4 a4 = arow[k4];
        a4.x = fmaxf(a4.x, 0.f);
        a4.y = fmaxf(a4.y, 0.f);
        a4.z = fmaxf(a4.z, 0.f);
        a4.w = fmaxf(a4.w, 0.f);
        float av[4] = {a4.x, a4.y, a4.z, a4.w};
#pragma unroll
        for (int kk = 0; kk < 4; kk++) {
            float a = av[kk];
            const float4* br = (const float4*)(Bs + (k4 * 4 + kk) * 64);
#pragma unroll
            for (int c = 0; c < 16; c++) {
                float4 b = br[c];
                acc[c].x = fmaf(a, b.x, acc[c].x);
                acc[c].y = fmaf(a, b.y, acc[c].y);
                acc[c].z = fmaf(a, b.z, acc[c].z);
                acc[c].w = fmaf(a, b.w, acc[c].w);
            }
        }
    }
    float4* crow = (float4*)(g_Z2 + (size_t)row * H_DIM);
#pragma unroll
    for (int c = 0; c < 16; c++) crow[c] = acc[c];
}

// ---------------- CSR aggregation 2: warp per node, writes d_out directly ----
// out[v] = bias + dinv[v]^2 * Z2[v] + sum_e w_e * Z2[src_e]
__global__ __launch_bounds__(256) void k_agg2_csr(const float* __restrict__ bmu,
                                                  const float* __restrict__ blog,
                                                  float* __restrict__ outMu,
                                                  float* __restrict__ outLog, int n) {
    int warp = (blockIdx.x * 256 + threadIdx.x) >> 5;
    int lane = threadIdx.x & 31;
    if (warp >= n) return;
    int rs = g_row[warp], re = g_row[warp + 1];
    float dv = g_dinv[warp];
    float s2 = dv * dv;
    const float2* zb = (const float2*)g_Z2;
    float2 zs = zb[(size_t)warp * 32 + lane];
    // lane cols [2*lane, 2*lane+1]: lanes 0..15 -> mu, 16..31 -> log
    const float* bp = (lane < 16) ? bmu : blog;
    float2 b = ((const float2*)bp)[lane & 15];
    float2 acc = make_float2(fmaf(zs.x, s2, b.x), fmaf(zs.y, s2, b.y));
    for (int e = rs; e < re; e++) {
        int2 ed = g_csr[e];
        float w = __int_as_float(ed.y);
        float2 z = zb[(size_t)ed.x * 32 + lane];
        acc.x = fmaf(w, z.x, acc.x);
        acc.y = fmaf(w, z.y, acc.y);
    }
    float* op = ((lane < 16) ? outMu : outLog) + (size_t)warp * OUT_DIM + (lane & 15) * 2;
    *(float2*)op = acc;
}

// ---------------- launch -----------------------------------------------------
extern "C" void kernel_launch(void* const* d_in, const int* in_sizes, int n_in,
                              void* d_out, int out_size) {
    const float* x    = (const float*)d_in[0];
    const int*   eraw = (const int*)d_in[1];
    const float* W1   = (const float*)d_in[2];
    const float* b1   = (const float*)d_in[3];
    const float* Wmu  = (const float*)d_in[4];
    const float* bmu  = (const float*)d_in[5];
    const float* Wlog = (const float*)d_in[6];
    const float* blog = (const float*)d_in[7];

    int N = in_sizes[0] / IN_DIM;   // 100000
    int E = in_sizes[1] / 2;        // 1600000
    if (N > MAXN) N = MAXN;
    if (E > MAXE) E = MAXE;

    float* outMu  = (float*)d_out;
    float* outLog = (float*)d_out + (size_t)N * OUT_DIM;

    const int T = 256;
    int gN  = (N + T - 1) / T;
    int gE  = (E + T - 1) / T;
    int gEN = ((E > N ? E : N) + T - 1) / T;
    int gW  = (N * 32 + T - 1) / T;     // warp-per-node grids

    // CSR build
    k_probe<<<1, 256>>>(eraw, 2 * E);
    k_extract<<<gEN, T>>>(eraw, E, N);
    k_count<<<gE, T>>>(E);
    k_scan<<<1, 1024>>>(N);
    k_dinv<<<gN, T>>>(N);
    k_scatter<<<gE, T>>>(E);

    // layer 1
    k_gemm1<<<gN, T>>>(x, W1, N);
    k_agg1_csr<<<gW, T>>>(b1, N);

    // layer 2 (mu|log fused), aggregation writes d_out directly
    k_gemm2<<<gN, T>>>(Wmu, Wlog, N);
    k_agg2_csr<<<gW, T>>>(bmu, blog, outMu, outLog, N);
}

// round 8
// speedup vs baseline: 2.1449x; 1.5540x over previous
#include <cuda_runtime.h>

// Problem-fixed dims: N=100000, E=1600000, IN=128, H=64, OUT=32
#define MAXN 100000
#define MAXE 1600000
#define IN_DIM 128
#define H_DIM 64
#define OUT_DIM 32
#define SCAN_B 1024
#define MAX_BLK ((MAXN + SCAN_B - 1) / SCAN_B)   // 98

// ---------------- scratch (device globals; no allocation allowed) ------------
__device__ int   g_is64;                       // edge_index dtype flag
__device__ __align__(16) int   g_src [MAXE];
__device__ __align__(16) int   g_dst [MAXE];
__device__ __align__(16) int   g_cnt [MAXN];   // in-degree (excl self-loop)
__device__ __align__(16) int   g_row [MAXN + 1];
__device__ __align__(16) int   g_cur [MAXN];
__device__ __align__(16) int   g_bsum[MAX_BLK];
__device__ __align__(16) int   g_boff[MAX_BLK];
__device__ __align__(16) float g_dinv[MAXN];
__device__ __align__(16) int2  g_csr [MAXE];   // (src, norm-bits) sorted by dst
__device__ __align__(16) float g_Z1[(size_t)MAXN * H_DIM]; // x@W1
__device__ __align__(16) float g_h [(size_t)MAXN * H_DIM]; // conv1 out (pre-relu)
__device__ __align__(16) float g_Z2[(size_t)MAXN * H_DIM]; // relu(h)@[Wmu|Wlog]

// ---------------- dtype probe ------------------------------------------------
__global__ void k_probe(const int* __restrict__ raw, int total_i32) {
    __shared__ int nz;
    if (threadIdx.x == 0) nz = 0;
    __syncthreads();
    int K = 2048;
    if (K > total_i32) K = total_i32;
    int cnt = 0;
    for (int i = 2 * threadIdx.x + 1; i < K; i += 2 * blockDim.x)
        if (raw[i] != 0) cnt++;
    if (cnt) atomicAdd(&nz, cnt);
    __syncthreads();
    if (threadIdx.x == 0) g_is64 = (nz == 0) ? 1 : 0;
}

// ---------------- extract + clamp edges, zero counts -------------------------
__global__ void k_extract(const int* __restrict__ raw, int E, int n) {
    int i = blockIdx.x * blockDim.x + threadIdx.x;
    if (i < n) g_cnt[i] = 0;
    if (i >= E) return;
    int s, d;
    if (g_is64) {
        const long long* e64 = (const long long*)raw;
        s = (int)e64[i];
        d = (int)e64[(size_t)E + i];
    } else {
        s = raw[i];
        d = raw[E + i];
    }
    if ((unsigned)s >= (unsigned)n) s = 0;
    if ((unsigned)d >= (unsigned)n) d = 0;
    g_src[i] = s;
    g_dst[i] = d;
}

__global__ void k_count(int E) {
    int i = blockIdx.x * blockDim.x + threadIdx.x;
    if (i < E) atomicAdd(&g_cnt[g_dst[i]], 1);
}

// ---------------- hierarchical exclusive scan of g_cnt -----------------------
// Phase A: per-block inclusive scan (1024 elems); store exclusive-in-block into
// g_row, block total into g_bsum.
__global__ __launch_bounds__(SCAN_B) void k_scanA(int n) {
    __shared__ int sh[SCAN_B];
    int t = threadIdx.x;
    int i = blockIdx.x * SCAN_B + t;
    int v = (i < n) ? g_cnt[i] : 0;
    sh[t] = v;
    __syncthreads();
#pragma unroll
    for (int off = 1; off < SCAN_B; off <<= 1) {
        int u = (t >= off) ? sh[t - off] : 0;
        __syncthreads();
        sh[t] += u;
        __syncthreads();
    }
    if (i < n) g_row[i] = sh[t] - v;    // exclusive within block
    if (t == SCAN_B - 1) g_bsum[blockIdx.x] = sh[t];
}

// Phase B: scan block totals (<=98 of them) in one small block.
__global__ __launch_bounds__(128) void k_scanB(int nblk, int n) {
    __shared__ int sh[128];
    int t = threadIdx.x;
    int v = (t < nblk) ? g_bsum[t] : 0;
    sh[t] = v;
    __syncthreads();
#pragma unroll
    for (int off = 1; off < 128; off <<= 1) {
        int u = (t >= off) ? sh[t - off] : 0;
        __syncthreads();
        sh[t] += u;
        __syncthreads();
    }
    if (t < nblk) g_boff[t] = sh[t] - v;  // exclusive prefix of block totals
    if (t == 127) g_row[n] = sh[127];     // grand total
}

// Phase C: add block offsets; mirror into g_cur.
__global__ __launch_bounds__(SCAN_B) void k_scanC(int n) {
    int i = blockIdx.x * SCAN_B + threadIdx.x;
    if (i < n) {
        int r = g_row[i] + g_boff[blockIdx.x];
        g_row[i] = r;
        g_cur[i] = r;
    }
}

__global__ void k_dinv(int n) {
    int i = blockIdx.x * blockDim.x + threadIdx.x;
    if (i < n) g_dinv[i] = rsqrtf(1.0f + (float)g_cnt[i]);  // +1 self-loop
}

// ---------------- scatter into CSR (norm computed here) ----------------------
__global__ void k_scatter(int E) {
    int i = blockIdx.x * blockDim.x + threadIdx.x;
    if (i >= E) return;
    int s = g_src[i], d = g_dst[i];
    float w = g_dinv[s] * g_dinv[d];
    int pos = atomicAdd(&g_cur[d], 1);
    g_csr[pos] = make_int2(s, __float_as_int(w));
}

// ---------------- GEMM1: Z1 = x @ W1   [N,128]x[128,64] ---------------------
__global__ __launch_bounds__(256) void k_gemm1(const float* __restrict__ x,
                                               const float* __restrict__ W1, int n) {
    __shared__ float Bs[IN_DIM * H_DIM];  // 32 KB
    int tid = threadIdx.x;
    for (int i = tid; i < IN_DIM * H_DIM; i += 256) Bs[i] = W1[i];
    __syncthreads();
    int row = blockIdx.x * 256 + tid;
    if (row >= n) return;

    float4 acc[16];
#pragma unroll
    for (int i = 0; i < 16; i++) acc[i] = make_float4(0.f, 0.f, 0.f, 0.f);

    const float4* arow = (const float4*)(x + (size_t)row * IN_DIM);
#pragma unroll 2
    for (int k4 = 0; k4 < IN_DIM / 4; k4++) {
        float4 a4 = arow[k4];
        float av[4] = {a4.x, a4.y, a4.z, a4.w};
#pragma unroll
        for (int kk = 0; kk < 4; kk++) {
            float a = av[kk];
            const float4* br = (const float4*)(Bs + (k4 * 4 + kk) * H_DIM);
#pragma unroll
            for (int c = 0; c < 16; c++) {
                float4 b = br[c];
                acc[c].x = fmaf(a, b.x, acc[c].x);
                acc[c].y = fmaf(a, b.y, acc[c].y);
                acc[c].z = fmaf(a, b.z, acc[c].z);
                acc[c].w = fmaf(a, b.w, acc[c].w);
            }
        }
    }
    float4* crow = (float4*)(g_Z1 + (size_t)row * H_DIM);
#pragma unroll
    for (int c = 0; c < 16; c++) crow[c] = acc[c];
}

// ---------------- CSR aggregation 1: warp per dst node -----------------------
__global__ __launch_bounds__(256) void k_agg1_csr(const float* __restrict__ b1, int n) {
    int warp = (blockIdx.x * 256 + threadIdx.x) >> 5;
    int lane = threadIdx.x & 31;
    if (warp >= n) return;
    int rs = g_row[warp], re = g_row[warp + 1];
    float dv = g_dinv[warp];
    float s2 = dv * dv;
    const float2* zb = (const float2*)g_Z1;
    float2 zs = zb[(size_t)warp * 32 + lane];
    float2 b  = ((const float2*)b1)[lane];
    float2 acc = make_float2(fmaf(zs.x, s2, b.x), fmaf(zs.y, s2, b.y));
    for (int e = rs; e < re; e++) {
        int2 ed = g_csr[e];
        float w = __int_as_float(ed.y);
        float2 z = zb[(size_t)ed.x * 32 + lane];
        acc.x = fmaf(w, z.x, acc.x);
        acc.y = fmaf(w, z.y, acc.y);
    }
    ((float2*)g_h)[(size_t)warp * 32 + lane] = acc;
}

// ---------------- GEMM2: Z2 = relu(h) @ [Wmu|Wlog]  [N,64]x[64,64] ----------
__global__ __launch_bounds__(256) void k_gemm2(const float* __restrict__ Wmu,
                                               const float* __restrict__ Wlog, int n) {
    __shared__ float Bs[H_DIM * 64];  // cols 0..31 = Wmu, 32..63 = Wlog
    int tid = threadIdx.x;
    for (int i = tid; i < H_DIM * OUT_DIM; i += 256) {
        int k = i / OUT_DIM, c = i % OUT_DIM;
        Bs[k * 64 + c]      = Wmu[i];
        Bs[k * 64 + 32 + c] = Wlog[i];
    }
    __syncthreads();
    int row = blockIdx.x * 256 + tid;
    if (row >= n) return;

    float4 acc[16];
#pragma unroll
    for (int i = 0; i < 16; i++) acc[i] = make_float4(0.f, 0.f, 0.f, 0.f);

    const float4* arow = (const float4*)(g_h + (size_t)row * H_DIM);
#pragma unroll 2
    for (int k4 = 0; k4 < H_DIM / 4; k4++) {
        float4 a4 = arow[k4];
        a4.x = fmaxf(a4.x, 0.f);
        a4.y = fmaxf(a4.y, 0.f);
        a4.z = fmaxf(a4.z, 0.f);
        a4.w = fmaxf(a4.w, 0.f);
        float av[4] = {a4.x, a4.y, a4.z, a4.w};
#pragma unroll
        for (int kk = 0; kk < 4; kk++) {
            float a = av[kk];
            const float4* br = (const float4*)(Bs + (k4 * 4 + kk) * 64);
#pragma unroll
            for (int c = 0; c < 16; c++) {
                float4 b = br[c];
                acc[c].x = fmaf(a, b.x, acc[c].x);
                acc[c].y = fmaf(a, b.y, acc[c].y);
                acc[c].z = fmaf(a, b.z, acc[c].z);
                acc[c].w = fmaf(a, b.w, acc[c].w);
            }
        }
    }
    float4* crow = (float4*)(g_Z2 + (size_t)row * H_DIM);
#pragma unroll
    for (int c = 0; c < 16; c++) crow[c] = acc[c];
}

// ---------------- CSR aggregation 2: warp per node, writes d_out directly ----
__global__ __launch_bounds__(256) void k_agg2_csr(const float* __restrict__ bmu,
                                                  const float* __restrict__ blog,
                                                  float* __restrict__ outMu,
                                                  float* __restrict__ outLog, int n) {
    int warp = (blockIdx.x * 256 + threadIdx.x) >> 5;
    int lane = threadIdx.x & 31;
    if (warp >= n) return;
    int rs = g_row[warp], re = g_row[warp + 1];
    float dv = g_dinv[warp];
    float s2 = dv * dv;
    const float2* zb = (const float2*)g_Z2;
    float2 zs = zb[(size_t)warp * 32 + lane];
    const float* bp = (lane < 16) ? bmu : blog;
    float2 b = ((const float2*)bp)[lane & 15];
    float2 acc = make_float2(fmaf(zs.x, s2, b.x), fmaf(zs.y, s2, b.y));
    for (int e = rs; e < re; e++) {
        int2 ed = g_csr[e];
        float w = __int_as_float(ed.y);
        float2 z = zb[(size_t)ed.x * 32 + lane];
        acc.x = fmaf(w, z.x, acc.x);
        acc.y = fmaf(w, z.y, acc.y);
    }
    float* op = ((lane < 16) ? outMu : outLog) + (size_t)warp * OUT_DIM + (lane & 15) * 2;
    *(float2*)op = acc;
}

// ---------------- launch -----------------------------------------------------
extern "C" void kernel_launch(void* const* d_in, const int* in_sizes, int n_in,
                              void* d_out, int out_size) {
    const float* x    = (const float*)d_in[0];
    const int*   eraw = (const int*)d_in[1];
    const float* W1   = (const float*)d_in[2];
    const float* b1   = (const float*)d_in[3];
    const float* Wmu  = (const float*)d_in[4];
    const float* bmu  = (const float*)d_in[5];
    const float* Wlog = (const float*)d_in[6];
    const float* blog = (const float*)d_in[7];

    int N = in_sizes[0] / IN_DIM;   // 100000
    int E = in_sizes[1] / 2;        // 1600000
    if (N > MAXN) N = MAXN;
    if (E > MAXE) E = MAXE;

    float* outMu  = (float*)d_out;
    float* outLog = (float*)d_out + (size_t)N * OUT_DIM;

    const int T = 256;
    int gN   = (N + T - 1) / T;
    int gE   = (E + T - 1) / T;
    int gEN  = ((E > N ? E : N) + T - 1) / T;
    int gW   = (N * 32 + T - 1) / T;          // warp-per-node grids
    int nblk = (N + SCAN_B - 1) / SCAN_B;     // scan blocks (98)

    // CSR build
    k_probe<<<1, 256>>>(eraw, 2 * E);
    k_extract<<<gEN, T>>>(eraw, E, N);
    k_count<<<gE, T>>>(E);
    k_scanA<<<nblk, SCAN_B>>>(N);
    k_scanB<<<1, 128>>>(nblk, N);
    k_scanC<<<nblk, SCAN_B>>>(N);
    k_dinv<<<gN, T>>>(N);
    k_scatter<<<gE, T>>>(E);

    // layer 1
    k_gemm1<<<gN, T>>>(x, W1, N);
    k_agg1_csr<<<gW, T>>>(b1, N);

    // layer 2 (mu|log fused), aggregation writes d_out directly
    k_gemm2<<<gN, T>>>(Wmu, Wlog, N);
    k_agg2_csr<<<gW, T>>>(bmu, blog, outMu, outLog, N);
}

// round 9
// speedup vs baseline: 2.2016x; 1.0264x over previous
#include <cuda_runtime.h>

// Problem-fixed dims: N=100000, E=1600000, IN=128, H=64, OUT=32
#define MAXN 100000
#define MAXE 1600000
#define IN_DIM 128
#define H_DIM 64
#define OUT_DIM 32
#define SCAN_B 1024
#define MAX_BLK ((MAXN + SCAN_B - 1) / SCAN_B)   // 98

// ---------------- scratch (device globals; no allocation allowed) ------------
__device__ __align__(16) int   g_src [MAXE];
__device__ __align__(16) int   g_dst [MAXE];
__device__ __align__(16) int   g_cnt [MAXN];   // in-degree (excl self-loop)
__device__ __align__(16) int   g_row [MAXN + 1];
__device__ __align__(16) int   g_cur [MAXN];
__device__ __align__(16) int   g_bsum[MAX_BLK];
__device__ __align__(16) int   g_boff[MAX_BLK];
__device__ __align__(16) float g_dinv[MAXN];
__device__ __align__(16) int2  g_csr [MAXE];   // (src, norm-bits) grouped by dst
__device__ __align__(16) float g_Z1[(size_t)MAXN * H_DIM]; // x@W1
__device__ __align__(16) float g_h [(size_t)MAXN * H_DIM]; // conv1 out (pre-relu)
__device__ __align__(16) float g_Z2[(size_t)MAXN * H_DIM]; // relu(h)@[Wmu|Wlog]

// ---------------- zero counters ----------------------------------------------
__global__ void k_zero(int n) {
    int i = blockIdx.x * blockDim.x + threadIdx.x;
    if (i < n) g_cnt[i] = 0;
}

// ---------------- extract + clamp + count (dtype probed per block) -----------
// int64 little-endian values < 2^31 have all-zero odd 32-bit words; int32 real
// indices make odd words nonzero with overwhelming probability. Each block
// probes the first 2048 words (8KB, L2-hot) redundantly - no separate launch.
__global__ __launch_bounds__(256) void k_extract(const int* __restrict__ raw,
                                                 int E, int n) {
    __shared__ int nz;
    if (threadIdx.x == 0) nz = 0;
    __syncthreads();
    {
        int K = 2048;
        if (K > 2 * E) K = 2 * E;
        int cnt = 0;
        for (int i = 2 * threadIdx.x + 1; i < K; i += 2 * 256)
            if (raw[i] != 0) cnt++;
        if (cnt) atomicAdd(&nz, cnt);
    }
    __syncthreads();
    int is64 = (nz == 0);

    int i = blockIdx.x * 256 + threadIdx.x;
    if (i >= E) return;
    int s, d;
    if (is64) {
        const long long* e64 = (const long long*)raw;
        s = (int)e64[i];
        d = (int)e64[(size_t)E + i];
    } else {
        s = raw[i];
        d = raw[E + i];
    }
    if ((unsigned)s >= (unsigned)n) s = 0;
    if ((unsigned)d >= (unsigned)n) d = 0;
    g_src[i] = s;
    g_dst[i] = d;
    atomicAdd(&g_cnt[d], 1);    // fused degree count
}

// ---------------- hierarchical exclusive scan of g_cnt -----------------------
__global__ __launch_bounds__(SCAN_B) void k_scanA(int n) {
    __shared__ int sh[SCAN_B];
    int t = threadIdx.x;
    int i = blockIdx.x * SCAN_B + t;
    int v = (i < n) ? g_cnt[i] : 0;
    sh[t] = v;
    __syncthreads();
#pragma unroll
    for (int off = 1; off < SCAN_B; off <<= 1) {
        int u = (t >= off) ? sh[t - off] : 0;
        __syncthreads();
        sh[t] += u;
        __syncthreads();
    }
    if (i < n) g_row[i] = sh[t] - v;    // exclusive within block
    if (t == SCAN_B - 1) g_bsum[blockIdx.x] = sh[t];
}

__global__ __launch_bounds__(128) void k_scanB(int nblk, int n) {
    __shared__ int sh[128];
    int t = threadIdx.x;
    int v = (t < nblk) ? g_bsum[t] : 0;
    sh[t] = v;
    __syncthreads();
#pragma unroll
    for (int off = 1; off < 128; off <<= 1) {
        int u = (t >= off) ? sh[t - off] : 0;
        __syncthreads();
        sh[t] += u;
        __syncthreads();
    }
    if (t < nblk) g_boff[t] = sh[t] - v;
    if (t == 127) g_row[n] = sh[127];
}

// Phase C: add block offsets; mirror into g_cur; fused dinv.
__global__ __launch_bounds__(SCAN_B) void k_scanC(int n) {
    int i = blockIdx.x * SCAN_B + threadIdx.x;
    if (i < n) {
        int r = g_row[i] + g_boff[blockIdx.x];
        g_row[i] = r;
        g_cur[i] = r;
        g_dinv[i] = rsqrtf(1.0f + (float)g_cnt[i]);  // +1 self-loop
    }
}

// ---------------- scatter into CSR (norm computed here) ----------------------
__global__ void k_scatter(int E) {
    int i = blockIdx.x * blockDim.x + threadIdx.x;
    if (i >= E) return;
    int s = g_src[i], d = g_dst[i];
    float w = g_dinv[s] * g_dinv[d];
    int pos = atomicAdd(&g_cur[d], 1);
    g_csr[pos] = make_int2(s, __float_as_int(w));
}

// ---------------- GEMM1: Z1 = x @ W1   [N,128]x[128,64] ---------------------
__global__ __launch_bounds__(256) void k_gemm1(const float* __restrict__ x,
                                               const float* __restrict__ W1, int n) {
    __shared__ float Bs[IN_DIM * H_DIM];  // 32 KB
    int tid = threadIdx.x;
    for (int i = tid; i < IN_DIM * H_DIM; i += 256) Bs[i] = W1[i];
    __syncthreads();
    int row = blockIdx.x * 256 + tid;
    if (row >= n) return;

    float4 acc[16];
#pragma unroll
    for (int i = 0; i < 16; i++) acc[i] = make_float4(0.f, 0.f, 0.f, 0.f);

    const float4* arow = (const float4*)(x + (size_t)row * IN_DIM);
#pragma unroll 2
    for (int k4 = 0; k4 < IN_DIM / 4; k4++) {
        float4 a4 = arow[k4];
        float av[4] = {a4.x, a4.y, a4.z, a4.w};
#pragma unroll
        for (int kk = 0; kk < 4; kk++) {
            float a = av[kk];
            const float4* br = (const float4*)(Bs + (k4 * 4 + kk) * H_DIM);
#pragma unroll
            for (int c = 0; c < 16; c++) {
                float4 b = br[c];
                acc[c].x = fmaf(a, b.x, acc[c].x);
                acc[c].y = fmaf(a, b.y, acc[c].y);
                acc[c].z = fmaf(a, b.z, acc[c].z);
                acc[c].w = fmaf(a, b.w, acc[c].w);
            }
        }
    }
    float4* crow = (float4*)(g_Z1 + (size_t)row * H_DIM);
#pragma unroll
    for (int c = 0; c < 16; c++) crow[c] = acc[c];
}

// ---------------- CSR aggregation 1: warp per dst node, 2 edges/iter ---------
// Half-warps process alternating edges with float4 lanes; combine via shfl.
__global__ __launch_bounds__(256) void k_agg1_csr(const float* __restrict__ b1, int n) {
    int warp = (blockIdx.x * 256 + threadIdx.x) >> 5;
    int lane = threadIdx.x & 31;
    if (warp >= n) return;
    int half = lane >> 4, l16 = lane & 15;
    int rs = g_row[warp], re = g_row[warp + 1];
    const float4* zb = (const float4*)g_Z1;

    float4 acc;
    if (half == 0) {   // seed self-loop + bias once
        float dv = g_dinv[warp];
        float s2 = dv * dv;
        float4 zs = zb[(size_t)warp * 16 + l16];
        float4 b  = ((const float4*)b1)[l16];
        acc = make_float4(fmaf(zs.x, s2, b.x), fmaf(zs.y, s2, b.y),
                          fmaf(zs.z, s2, b.z), fmaf(zs.w, s2, b.w));
    } else {
        acc = make_float4(0.f, 0.f, 0.f, 0.f);
    }
    for (int e = rs + half; e < re; e += 2) {
        int2 ed = g_csr[e];
        float w = __int_as_float(ed.y);
        float4 z = zb[(size_t)ed.x * 16 + l16];
        acc.x = fmaf(w, z.x, acc.x);
        acc.y = fmaf(w, z.y, acc.y);
        acc.z = fmaf(w, z.z, acc.z);
        acc.w = fmaf(w, z.w, acc.w);
    }
    acc.x += __shfl_xor_sync(0xffffffffu, acc.x, 16);
    acc.y += __shfl_xor_sync(0xffffffffu, acc.y, 16);
    acc.z += __shfl_xor_sync(0xffffffffu, acc.z, 16);
    acc.w += __shfl_xor_sync(0xffffffffu, acc.w, 16);
    if (half == 0)
        ((float4*)g_h)[(size_t)warp * 16 + l16] = acc;
}

// ---------------- GEMM2: Z2 = relu(h) @ [Wmu|Wlog]  [N,64]x[64,64] ----------
__global__ __launch_bounds__(256) void k_gemm2(const float* __restrict__ Wmu,
                                               const float* __restrict__ Wlog, int n) {
    __shared__ float Bs[H_DIM * 64];  // cols 0..31 = Wmu, 32..63 = Wlog
    int tid = threadIdx.x;
    for (int i = tid; i < H_DIM * OUT_DIM; i += 256) {
        int k = i / OUT_DIM, c = i % OUT_DIM;
        Bs[k * 64 + c]      = Wmu[i];
        Bs[k * 64 + 32 + c] = Wlog[i];
    }
    __syncthreads();
    int row = blockIdx.x * 256 + tid;
    if (row >= n) return;

    float4 acc[16];
#pragma unroll
    for (int i = 0; i < 16; i++) acc[i] = make_float4(0.f, 0.f, 0.f, 0.f);

    const float4* arow = (const float4*)(g_h + (size_t)row * H_DIM);
#pragma unroll 2
    for (int k4 = 0; k4 < H_DIM / 4; k4++) {
        float4 a4 = arow[k4];
        a4.x = fmaxf(a4.x, 0.f);
        a4.y = fmaxf(a4.y, 0.f);
        a4.z = fmaxf(a4.z, 0.f);
        a4.w = fmaxf(a4.w, 0.f);
        float av[4] = {a4.x, a4.y, a4.z, a4.w};
#pragma unroll
        for (int kk = 0; kk < 4; kk++) {
            float a = av[kk];
            const float4* br = (const float4*)(Bs + (k4 * 4 + kk) * 64);
#pragma unroll
            for (int c = 0; c < 16; c++) {
                float4 b = br[c];
                acc[c].x = fmaf(a, b.x, acc[c].x);
                acc[c].y = fmaf(a, b.y, acc[c].y);
                acc[c].z = fmaf(a, b.z, acc[c].z);
                acc[c].w = fmaf(a, b.w, acc[c].w);
            }
        }
    }
    float4* crow = (float4*)(g_Z2 + (size_t)row * H_DIM);
#pragma unroll
    for (int c = 0; c < 16; c++) crow[c] = acc[c];
}

// ---------------- CSR aggregation 2: warp per node -> d_out ------------------
__global__ __launch_bounds__(256) void k_agg2_csr(const float* __restrict__ bmu,
                                                  const float* __restrict__ blog,
                                                  float* __restrict__ outMu,
                                                  float* __restrict__ outLog, int n) {
    int warp = (blockIdx.x * 256 + threadIdx.x) >> 5;
    int lane = threadIdx.x & 31;
    if (warp >= n) return;
    int half = lane >> 4, l16 = lane & 15;
    int rs = g_row[warp], re = g_row[warp + 1];
    const float4* zb = (const float4*)g_Z2;

    float4 acc;
    if (half == 0) {
        float dv = g_dinv[warp];
        float s2 = dv * dv;
        float4 zs = zb[(size_t)warp * 16 + l16];
        float4 b = (l16 < 8) ? ((const float4*)bmu)[l16]
                             : ((const float4*)blog)[l16 - 8];
        acc = make_float4(fmaf(zs.x, s2, b.x), fmaf(zs.y, s2, b.y),
                          fmaf(zs.z, s2, b.z), fmaf(zs.w, s2, b.w));
    } else {
        acc = make_float4(0.f, 0.f, 0.f, 0.f);
    }
    for (int e = rs + half; e < re; e += 2) {
        int2 ed = g_csr[e];
        float w = __int_as_float(ed.y);
        float4 z = zb[(size_t)ed.x * 16 + l16];
        acc.x = fmaf(w, z.x, acc.x);
        acc.y = fmaf(w, z.y, acc.y);
        acc.z = fmaf(w, z.z, acc.z);
        acc.w = fmaf(w, z.w, acc.w);
    }
    acc.x += __shfl_xor_sync(0xffffffffu, acc.x, 16);
    acc.y += __shfl_xor_sync(0xffffffffu, acc.y, 16);
    acc.z += __shfl_xor_sync(0xffffffffu, acc.z, 16);
    acc.w += __shfl_xor_sync(0xffffffffu, acc.w, 16);
    if (half == 0) {
        if (l16 < 8)
            ((float4*)(outMu + (size_t)warp * OUT_DIM))[l16] = acc;
        else
            ((float4*)(outLog + (size_t)warp * OUT_DIM))[l16 - 8] = acc;
    }
}

// ---------------- launch -----------------------------------------------------
extern "C" void kernel_launch(void* const* d_in, const int* in_sizes, int n_in,
                              void* d_out, int out_size) {
    const float* x    = (const float*)d_in[0];
    const int*   eraw = (const int*)d_in[1];
    const float* W1   = (const float*)d_in[2];
    const float* b1   = (const float*)d_in[3];
    const float* Wmu  = (const float*)d_in[4];
    const float* bmu  = (const float*)d_in[5];
    const float* Wlog = (const float*)d_in[6];
    const float* blog = (const float*)d_in[7];

    int N = in_sizes[0] / IN_DIM;   // 100000
    int E = in_sizes[1] / 2;        // 1600000
    if (N > MAXN) N = MAXN;
    if (E > MAXE) E = MAXE;

    float* outMu  = (float*)d_out;
    float* outLog = (float*)d_out + (size_t)N * OUT_DIM;

    const int T = 256;
    int gN   = (N + T - 1) / T;
    int gE   = (E + T - 1) / T;
    int gW   = (N * 32 + T - 1) / T;          // warp-per-node grids
    int nblk = (N + SCAN_B - 1) / SCAN_B;     // scan blocks (98)

    // CSR build
    k_zero<<<gN, T>>>(N);
    k_extract<<<gE, T>>>(eraw, E, N);         // probe + extract + count fused
    k_scanA<<<nblk, SCAN_B>>>(N);
    k_scanB<<<1, 128>>>(nblk, N);
    k_scanC<<<nblk, SCAN_B>>>(N);             // offsets + g_cur + dinv fused
    k_scatter<<<gE, T>>>(E);

    // layer 1
    k_gemm1<<<gN, T>>>(x, W1, N);
    k_agg1_csr<<<gW, T>>>(b1, N);

    // layer 2 (mu|log fused), aggregation writes d_out directly
    k_gemm2<<<gN, T>>>(Wmu, Wlog, N);
    k_agg2_csr<<<gW, T>>>(bmu, blog, outMu, outLog, N);
}

// round 10
// speedup vs baseline: 2.2791x; 1.0352x over previous
#include <cuda_runtime.h>

// Problem-fixed dims: N=100000, E=1600000, IN=128, H=64, OUT=32
#define MAXN 100000
#define MAXE 1600000
#define IN_DIM 128
#define H_DIM 64
#define OUT_DIM 32
#define SCAN_B 1024
#define MAX_BLK ((MAXN + SCAN_B - 1) / SCAN_B)   // 98

typedef unsigned long long ull;

// ---------------- scratch (device globals; no allocation allowed) ------------
__device__ __align__(16) int   g_cnt [MAXN];   // in-degree (excl self-loop)
__device__ __align__(16) int   g_row [MAXN + 1];
__device__ __align__(16) int   g_cur [MAXN];
__device__ __align__(16) int   g_bsum[MAX_BLK];
__device__ __align__(16) int   g_boff[MAX_BLK];
__device__ __align__(16) float g_dinv[MAXN];
__device__ __align__(16) int2  g_csr [MAXE];   // (src, norm-bits) grouped by dst
__device__ __align__(16) float g_Z1[(size_t)MAXN * H_DIM]; // x@W1
__device__ __align__(16) float g_h [(size_t)MAXN * H_DIM]; // conv1 out (pre-relu)
__device__ __align__(16) float g_Z2[(size_t)MAXN * H_DIM]; // relu(h)@[Wmu|Wlog]

// ---------------- f32x2 packed FMA helpers -----------------------------------
__device__ __forceinline__ ull pack_dup(float a) {
    ull r;
    asm("mov.b64 %0, {%1, %1};" : "=l"(r) : "r"(__float_as_uint(a)));
    return r;
}
#define FMA2(acc, a2, b2) \
    asm("fma.rn.f32x2 %0, %1, %2, %0;" : "+l"(acc) : "l"(a2), "l"(b2))

// ---------------- dtype probe helper (per-block, L2-hot, ~free) --------------
// int64 little-endian values < 2^31 have all-zero odd 32-bit words; int32 real
// indices make odd words nonzero with overwhelming probability.
__device__ __forceinline__ int probe_is64(const int* __restrict__ raw, int E,
                                          int* sh_nz) {
    if (threadIdx.x == 0) *sh_nz = 0;
    __syncthreads();
    int K = 2048;
    if (K > 2 * E) K = 2 * E;
    int cnt = 0;
    for (int i = 2 * threadIdx.x + 1; i < K; i += 2 * blockDim.x)
        if (raw[i] != 0) cnt++;
    if (cnt) atomicAdd(sh_nz, cnt);
    __syncthreads();
    return (*sh_nz == 0);
}

// ---------------- zero counters ----------------------------------------------
__global__ void k_zero(int n) {
    int i = blockIdx.x * blockDim.x + threadIdx.x;
    if (i < n) g_cnt[i] = 0;
}

// ---------------- count in-degrees straight from raw edge list ---------------
__global__ __launch_bounds__(256) void k_count(const int* __restrict__ raw,
                                               int E, int n) {
    __shared__ int nz;
    int is64 = probe_is64(raw, E, &nz);
    int i = blockIdx.x * 256 + threadIdx.x;
    if (i >= E) return;
    int d = is64 ? (int)((const long long*)raw)[(size_t)E + i] : raw[E + i];
    if ((unsigned)d >= (unsigned)n) d = 0;
    atomicAdd(&g_cnt[d], 1);
}

// ---------------- hierarchical exclusive scan of g_cnt -----------------------
__global__ __launch_bounds__(SCAN_B) void k_scanA(int n) {
    __shared__ int sh[SCAN_B];
    int t = threadIdx.x;
    int i = blockIdx.x * SCAN_B + t;
    int v = (i < n) ? g_cnt[i] : 0;
    sh[t] = v;
    __syncthreads();
#pragma unroll
    for (int off = 1; off < SCAN_B; off <<= 1) {
        int u = (t >= off) ? sh[t - off] : 0;
        __syncthreads();
        sh[t] += u;
        __syncthreads();
    }
    if (i < n) g_row[i] = sh[t] - v;
    if (t == SCAN_B - 1) g_bsum[blockIdx.x] = sh[t];
}

__global__ __launch_bounds__(128) void k_scanB(int nblk, int n) {
    __shared__ int sh[128];
    int t = threadIdx.x;
    int v = (t < nblk) ? g_bsum[t] : 0;
    sh[t] = v;
    __syncthreads();
#pragma unroll
    for (int off = 1; off < 128; off <<= 1) {
        int u = (t >= off) ? sh[t - off] : 0;
        __syncthreads();
        sh[t] += u;
        __syncthreads();
    }
    if (t < nblk) g_boff[t] = sh[t] - v;
    if (t == 127) g_row[n] = sh[127];
}

// Phase C: add block offsets; mirror into g_cur; fused dinv.
__global__ __launch_bounds__(SCAN_B) void k_scanC(int n) {
    int i = blockIdx.x * SCAN_B + threadIdx.x;
    if (i < n) {
        int r = g_row[i] + g_boff[blockIdx.x];
        g_row[i] = r;
        g_cur[i] = r;
        g_dinv[i] = rsqrtf(1.0f + (float)g_cnt[i]);  // +1 self-loop
    }
}

// ---------------- scatter into CSR straight from raw (norm computed here) ----
__global__ __launch_bounds__(256) void k_scatter(const int* __restrict__ raw,
                                                 int E, int n) {
    __shared__ int nz;
    int is64 = probe_is64(raw, E, &nz);
    int i = blockIdx.x * 256 + threadIdx.x;
    if (i >= E) return;
    int s, d;
    if (is64) {
        const long long* e64 = (const long long*)raw;
        s = (int)e64[i];
        d = (int)e64[(size_t)E + i];
    } else {
        s = raw[i];
        d = raw[E + i];
    }
    if ((unsigned)s >= (unsigned)n) s = 0;
    if ((unsigned)d >= (unsigned)n) d = 0;
    float w = g_dinv[s] * g_dinv[d];
    int pos = atomicAdd(&g_cur[d], 1);
    g_csr[pos] = make_int2(s, __float_as_int(w));
}

// ---------------- GEMM1: Z1 = x @ W1   [N,128]x[128,64], f32x2 FMA ----------
__global__ __launch_bounds__(256) void k_gemm1(const float* __restrict__ x,
                                               const float* __restrict__ W1, int n) {
    __shared__ __align__(16) float Bs[IN_DIM * H_DIM];  // 32 KB
    int tid = threadIdx.x;
    for (int i = tid; i < IN_DIM * H_DIM; i += 256) Bs[i] = W1[i];
    __syncthreads();
    int row = blockIdx.x * 256 + tid;
    if (row >= n) return;

    ull acc[32];   // 64 cols as 32 packed f32x2
#pragma unroll
    for (int i = 0; i < 32; i++) acc[i] = 0ull;

    const float4* arow = (const float4*)(x + (size_t)row * IN_DIM);
#pragma unroll 2
    for (int k4 = 0; k4 < IN_DIM / 4; k4++) {
        float4 a4 = arow[k4];
        float av[4] = {a4.x, a4.y, a4.z, a4.w};
#pragma unroll
        for (int kk = 0; kk < 4; kk++) {
            ull a2 = pack_dup(av[kk]);
            const ull* br = (const ull*)(Bs + (k4 * 4 + kk) * H_DIM);
#pragma unroll
            for (int c = 0; c < 32; c++) FMA2(acc[c], a2, br[c]);
        }
    }
    longlong2* crow = (longlong2*)(g_Z1 + (size_t)row * H_DIM);
#pragma unroll
    for (int c = 0; c < 16; c++) {
        longlong2 v;
        v.x = (long long)acc[2 * c];
        v.y = (long long)acc[2 * c + 1];
        crow[c] = v;
    }
}

// ---------------- CSR aggregation 1: warp per dst node, 2 edges/iter ---------
__global__ __launch_bounds__(256) void k_agg1_csr(const float* __restrict__ b1, int n) {
    int warp = (blockIdx.x * 256 + threadIdx.x) >> 5;
    int lane = threadIdx.x & 31;
    if (warp >= n) return;
    int half = lane >> 4, l16 = lane & 15;
    int rs = g_row[warp], re = g_row[warp + 1];
    const float4* zb = (const float4*)g_Z1;

    float4 acc;
    if (half == 0) {   // seed self-loop + bias once
        float dv = g_dinv[warp];
        float s2 = dv * dv;
        float4 zs = zb[(size_t)warp * 16 + l16];
        float4 b  = ((const float4*)b1)[l16];
        acc = make_float4(fmaf(zs.x, s2, b.x), fmaf(zs.y, s2, b.y),
                          fmaf(zs.z, s2, b.z), fmaf(zs.w, s2, b.w));
    } else {
        acc = make_float4(0.f, 0.f, 0.f, 0.f);
    }
    for (int e = rs + half; e < re; e += 2) {
        int2 ed = g_csr[e];
        float w = __int_as_float(ed.y);
        float4 z = zb[(size_t)ed.x * 16 + l16];
        acc.x = fmaf(w, z.x, acc.x);
        acc.y = fmaf(w, z.y, acc.y);
        acc.z = fmaf(w, z.z, acc.z);
        acc.w = fmaf(w, z.w, acc.w);
    }
    acc.x += __shfl_xor_sync(0xffffffffu, acc.x, 16);
    acc.y += __shfl_xor_sync(0xffffffffu, acc.y, 16);
    acc.z += __shfl_xor_sync(0xffffffffu, acc.z, 16);
    acc.w += __shfl_xor_sync(0xffffffffu, acc.w, 16);
    if (half == 0)
        ((float4*)g_h)[(size_t)warp * 16 + l16] = acc;
}

// ---------------- GEMM2: Z2 = relu(h) @ [Wmu|Wlog], f32x2 FMA ---------------
__global__ __launch_bounds__(256) void k_gemm2(const float* __restrict__ Wmu,
                                               const float* __restrict__ Wlog, int n) {
    __shared__ __align__(16) float Bs[H_DIM * 64];  // cols 0..31 Wmu, 32..63 Wlog
    int tid = threadIdx.x;
    for (int i = tid; i < H_DIM * OUT_DIM; i += 256) {
        int k = i / OUT_DIM, c = i % OUT_DIM;
        Bs[k * 64 + c]      = Wmu[i];
        Bs[k * 64 + 32 + c] = Wlog[i];
    }
    __syncthreads();
    int row = blockIdx.x * 256 + tid;
    if (row >= n) return;

    ull acc[32];
#pragma unroll
    for (int i = 0; i < 32; i++) acc[i] = 0ull;

    const float4* arow = (const float4*)(g_h + (size_t)row * H_DIM);
#pragma unroll 2
    for (int k4 = 0; k4 < H_DIM / 4; k4++) {
        float4 a4 = arow[k4];
        a4.x = fmaxf(a4.x, 0.f);
        a4.y = fmaxf(a4.y, 0.f);
        a4.z = fmaxf(a4.z, 0.f);
        a4.w = fmaxf(a4.w, 0.f);
        float av[4] = {a4.x, a4.y, a4.z, a4.w};
#pragma unroll
        for (int kk = 0; kk < 4; kk++) {
            ull a2 = pack_dup(av[kk]);
            const ull* br = (const ull*)(Bs + (k4 * 4 + kk) * 64);
#pragma unroll
            for (int c = 0; c < 32; c++) FMA2(acc[c], a2, br[c]);
        }
    }
    longlong2* crow = (longlong2*)(g_Z2 + (size_t)row * H_DIM);
#pragma unroll
    for (int c = 0; c < 16; c++) {
        longlong2 v;
        v.x = (long long)acc[2 * c];
        v.y = (long long)acc[2 * c + 1];
        crow[c] = v;
    }
}

// ---------------- CSR aggregation 2: warp per node -> d_out ------------------
__global__ __launch_bounds__(256) void k_agg2_csr(const float* __restrict__ bmu,
                                                  const float* __restrict__ blog,
                                                  float* __restrict__ outMu,
                                                  float* __restrict__ outLog, int n) {
    int warp = (blockIdx.x * 256 + threadIdx.x) >> 5;
    int lane = threadIdx.x & 31;
    if (warp >= n) return;
    int half = lane >> 4, l16 = lane & 15;
    int rs = g_row[warp], re = g_row[warp + 1];
    const float4* zb = (const float4*)g_Z2;

    float4 acc;
    if (half == 0) {
        float dv = g_dinv[warp];
        float s2 = dv * dv;
        float4 zs = zb[(size_t)warp * 16 + l16];
        float4 b = (l16 < 8) ? ((const float4*)bmu)[l16]
                             : ((const float4*)blog)[l16 - 8];
        acc = make_float4(fmaf(zs.x, s2, b.x), fmaf(zs.y, s2, b.y),
                          fmaf(zs.z, s2, b.z), fmaf(zs.w, s2, b.w));
    } else {
        acc = make_float4(0.f, 0.f, 0.f, 0.f);
    }
    for (int e = rs + half; e < re; e += 2) {
        int2 ed = g_csr[e];
        float w = __int_as_float(ed.y);
        float4 z = zb[(size_t)ed.x * 16 + l16];
        acc.x = fmaf(w, z.x, acc.x);
        acc.y = fmaf(w, z.y, acc.y);
        acc.z = fmaf(w, z.z, acc.z);
        acc.w = fmaf(w, z.w, acc.w);
    }
    acc.x += __shfl_xor_sync(0xffffffffu, acc.x, 16);
    acc.y += __shfl_xor_sync(0xffffffffu, acc.y, 16);
    acc.z += __shfl_xor_sync(0xffffffffu, acc.z, 16);
    acc.w += __shfl_xor_sync(0xffffffffu, acc.w, 16);
    if (half == 0) {
        if (l16 < 8)
            ((float4*)(outMu + (size_t)warp * OUT_DIM))[l16] = acc;
        else
            ((float4*)(outLog + (size_t)warp * OUT_DIM))[l16 - 8] = acc;
    }
}

// ---------------- launch -----------------------------------------------------
extern "C" void kernel_launch(void* const* d_in, const int* in_sizes, int n_in,
                              void* d_out, int out_size) {
    const float* x    = (const float*)d_in[0];
    const int*   eraw = (const int*)d_in[1];
    const float* W1   = (const float*)d_in[2];
    const float* b1   = (const float*)d_in[3];
    const float* Wmu  = (const float*)d_in[4];
    const float* bmu  = (const float*)d_in[5];
    const float* Wlog = (const float*)d_in[6];
    const float* blog = (const float*)d_in[7];

    int N = in_sizes[0] / IN_DIM;   // 100000
    int E = in_sizes[1] / 2;        // 1600000
    if (N > MAXN) N = MAXN;
    if (E > MAXE) E = MAXE;

    float* outMu  = (float*)d_out;
    float* outLog = (float*)d_out + (size_t)N * OUT_DIM;

    const int T = 256;
    int gN   = (N + T - 1) / T;
    int gE   = (E + T - 1) / T;
    int gW   = (N * 32 + T - 1) / T;          // warp-per-node grids
    int nblk = (N + SCAN_B - 1) / SCAN_B;     // scan blocks (98)

    // CSR build (no staging; raw edge list read twice, probe fused per block)
    k_zero<<<gN, T>>>(N);
    k_count<<<gE, T>>>(eraw, E, N);
    k_scanA<<<nblk, SCAN_B>>>(N);
    k_scanB<<<1, 128>>>(nblk, N);
    k_scanC<<<nblk, SCAN_B>>>(N);             // offsets + g_cur + dinv fused
    k_scatter<<<gE, T>>>(eraw, E, N);

    // layer 1
    k_gemm1<<<gN, T>>>(x, W1, N);
    k_agg1_csr<<<gW, T>>>(b1, N);

    // layer 2 (mu|log fused), aggregation writes d_out directly
    k_gemm2<<<gN, T>>>(Wmu, Wlog, N);
    k_agg2_csr<<<gW, T>>>(bmu, blog, outMu, outLog, N);
}

// round 11
// speedup vs baseline: 2.4022x; 1.0540x over previous
#include <cuda_runtime.h>

// Problem-fixed dims: N=100000, E=1600000, IN=128, H=64, OUT=32
#define MAXN 100000
#define MAXE 1600000
#define IN_DIM 128
#define H_DIM 64
#define OUT_DIM 32
#define SCAN_B 1024
#define MAX_BLK ((MAXN + SCAN_B - 1) / SCAN_B)   // 98

typedef unsigned long long ull;

// ---------------- scratch (device globals; no allocation allowed) ------------
__device__ __align__(16) int   g_cnt [MAXN];   // in-degree (excl self-loop)
__device__ __align__(16) int   g_row [MAXN + 1];
__device__ __align__(16) int   g_cur [MAXN];
__device__ __align__(16) int   g_bsum[MAX_BLK];
__device__ __align__(16) int   g_boff[MAX_BLK];
__device__ __align__(16) float g_dinv[MAXN];
__device__ __align__(16) int2  g_csr [MAXE];   // (src, norm-bits) grouped by dst
__device__ __align__(16) float g_Z1[(size_t)MAXN * H_DIM]; // x@W1
__device__ __align__(16) float g_h [(size_t)MAXN * H_DIM]; // conv1 out (pre-relu)
__device__ __align__(16) float g_Z2[(size_t)MAXN * H_DIM]; // relu(h)@[Wmu|Wlog]

// ---------------- f32x2 packed FMA helpers -----------------------------------
__device__ __forceinline__ ull pack_dup(float a) {
    ull r;
    asm("mov.b64 %0, {%1, %1};" : "=l"(r) : "r"(__float_as_uint(a)));
    return r;
}
#define FMA2(acc, a2, b2) \
    asm("fma.rn.f32x2 %0, %1, %2, %0;" : "+l"(acc) : "l"(a2), "l"(b2))

// ---------------- dtype probe helper (per-block, L2-hot, ~free) --------------
__device__ __forceinline__ int probe_is64(const int* __restrict__ raw, int E,
                                          int* sh_nz) {
    if (threadIdx.x == 0) *sh_nz = 0;
    __syncthreads();
    int K = 2048;
    if (K > 2 * E) K = 2 * E;
    int cnt = 0;
    for (int i = 2 * threadIdx.x + 1; i < K; i += 2 * blockDim.x)
        if (raw[i] != 0) cnt++;
    if (cnt) atomicAdd(sh_nz, cnt);
    __syncthreads();
    return (*sh_nz == 0);
}

// ---------------- zero counters ----------------------------------------------
__global__ void k_zero(int n) {
    int i = blockIdx.x * blockDim.x + threadIdx.x;
    if (i < n) g_cnt[i] = 0;
}

// ---------------- count in-degrees straight from raw edge list ---------------
__global__ __launch_bounds__(256) void k_count(const int* __restrict__ raw,
                                               int E, int n) {
    __shared__ int nz;
    int is64 = probe_is64(raw, E, &nz);
    int i = blockIdx.x * 256 + threadIdx.x;
    if (i >= E) return;
    int d = is64 ? (int)((const long long*)raw)[(size_t)E + i] : raw[E + i];
    if ((unsigned)d >= (unsigned)n) d = 0;
    atomicAdd(&g_cnt[d], 1);
}

// ---------------- hierarchical exclusive scan of g_cnt -----------------------
__global__ __launch_bounds__(SCAN_B) void k_scanA(int n) {
    __shared__ int sh[SCAN_B];
    int t = threadIdx.x;
    int i = blockIdx.x * SCAN_B + t;
    int v = (i < n) ? g_cnt[i] : 0;
    sh[t] = v;
    __syncthreads();
#pragma unroll
    for (int off = 1; off < SCAN_B; off <<= 1) {
        int u = (t >= off) ? sh[t - off] : 0;
        __syncthreads();
        sh[t] += u;
        __syncthreads();
    }
    if (i < n) g_row[i] = sh[t] - v;
    if (t == SCAN_B - 1) g_bsum[blockIdx.x] = sh[t];
}

__global__ __launch_bounds__(128) void k_scanB(int nblk, int n) {
    __shared__ int sh[128];
    int t = threadIdx.x;
    int v = (t < nblk) ? g_bsum[t] : 0;
    sh[t] = v;
    __syncthreads();
#pragma unroll
    for (int off = 1; off < 128; off <<= 1) {
        int u = (t >= off) ? sh[t - off] : 0;
        __syncthreads();
        sh[t] += u;
        __syncthreads();
    }
    if (t < nblk) g_boff[t] = sh[t] - v;
    if (t == 127) g_row[n] = sh[127];
}

// Phase C: add block offsets; mirror into g_cur; fused dinv.
__global__ __launch_bounds__(SCAN_B) void k_scanC(int n) {
    int i = blockIdx.x * SCAN_B + threadIdx.x;
    if (i < n) {
        int r = g_row[i] + g_boff[blockIdx.x];
        g_row[i] = r;
        g_cur[i] = r;
        g_dinv[i] = rsqrtf(1.0f + (float)g_cnt[i]);  // +1 self-loop
    }
}

// ---------------- scatter into CSR straight from raw (norm computed here) ----
__global__ __launch_bounds__(256) void k_scatter(const int* __restrict__ raw,
                                                 int E, int n) {
    __shared__ int nz;
    int is64 = probe_is64(raw, E, &nz);
    int i = blockIdx.x * 256 + threadIdx.x;
    if (i >= E) return;
    int s, d;
    if (is64) {
        const long long* e64 = (const long long*)raw;
        s = (int)e64[i];
        d = (int)e64[(size_t)E + i];
    } else {
        s = raw[i];
        d = raw[E + i];
    }
    if ((unsigned)s >= (unsigned)n) s = 0;
    if ((unsigned)d >= (unsigned)n) d = 0;
    float w = g_dinv[s] * g_dinv[d];
    int pos = atomicAdd(&g_cur[d], 1);
    g_csr[pos] = make_int2(s, __float_as_int(w));
}

// ---------------- GEMM1: Z1 = x @ W1   [N,128]x[128,64], f32x2 FMA ----------
__global__ __launch_bounds__(256) void k_gemm1(const float* __restrict__ x,
                                               const float* __restrict__ W1, int n) {
    __shared__ __align__(16) float Bs[IN_DIM * H_DIM];  // 32 KB
    int tid = threadIdx.x;
    for (int i = tid; i < IN_DIM * H_DIM; i += 256) Bs[i] = W1[i];
    __syncthreads();
    int row = blockIdx.x * 256 + tid;
    if (row >= n) return;

    ull acc[32];   // 64 cols as 32 packed f32x2
#pragma unroll
    for (int i = 0; i < 32; i++) acc[i] = 0ull;

    const float4* arow = (const float4*)(x + (size_t)row * IN_DIM);
#pragma unroll 2
    for (int k4 = 0; k4 < IN_DIM / 4; k4++) {
        float4 a4 = arow[k4];
        float av[4] = {a4.x, a4.y, a4.z, a4.w};
#pragma unroll
        for (int kk = 0; kk < 4; kk++) {
            ull a2 = pack_dup(av[kk]);
            const ull* br = (const ull*)(Bs + (k4 * 4 + kk) * H_DIM);
#pragma unroll
            for (int c = 0; c < 32; c++) FMA2(acc[c], a2, br[c]);
        }
    }
    longlong2* crow = (longlong2*)(g_Z1 + (size_t)row * H_DIM);
#pragma unroll
    for (int c = 0; c < 16; c++) {
        longlong2 v;
        v.x = (long long)acc[2 * c];
        v.y = (long long)acc[2 * c + 1];
        crow[c] = v;
    }
}

// ---------------- CSR aggregation 1: warp per dst node, 2 edges/iter ---------
__global__ __launch_bounds__(256) void k_agg1_csr(const float* __restrict__ b1, int n) {
    int warp = (blockIdx.x * 256 + threadIdx.x) >> 5;
    int lane = threadIdx.x & 31;
    if (warp >= n) return;
    int half = lane >> 4, l16 = lane & 15;
    int rs = g_row[warp], re = g_row[warp + 1];
    const float4* zb = (const float4*)g_Z1;

    float4 acc;
    if (half == 0) {   // seed self-loop + bias once
        float dv = g_dinv[warp];
        float s2 = dv * dv;
        float4 zs = zb[(size_t)warp * 16 + l16];
        float4 b  = ((const float4*)b1)[l16];
        acc = make_float4(fmaf(zs.x, s2, b.x), fmaf(zs.y, s2, b.y),
                          fmaf(zs.z, s2, b.z), fmaf(zs.w, s2, b.w));
    } else {
        acc = make_float4(0.f, 0.f, 0.f, 0.f);
    }
    for (int e = rs + half; e < re; e += 2) {
        int2 ed = g_csr[e];
        float w = __int_as_float(ed.y);
        float4 z = zb[(size_t)ed.x * 16 + l16];
        acc.x = fmaf(w, z.x, acc.x);
        acc.y = fmaf(w, z.y, acc.y);
        acc.z = fmaf(w, z.z, acc.z);
        acc.w = fmaf(w, z.w, acc.w);
    }
    acc.x += __shfl_xor_sync(0xffffffffu, acc.x, 16);
    acc.y += __shfl_xor_sync(0xffffffffu, acc.y, 16);
    acc.z += __shfl_xor_sync(0xffffffffu, acc.z, 16);
    acc.w += __shfl_xor_sync(0xffffffffu, acc.w, 16);
    if (half == 0)
        ((float4*)g_h)[(size_t)warp * 16 + l16] = acc;
}

// ---------------- GEMM2: Z2 = relu(h) @ [Wmu|Wlog], f32x2 FMA ---------------
__global__ __launch_bounds__(256) void k_gemm2(const float* __restrict__ Wmu,
                                               const float* __restrict__ Wlog, int n) {
    __shared__ __align__(16) float Bs[H_DIM * 64];  // cols 0..31 Wmu, 32..63 Wlog
    int tid = threadIdx.x;
    for (int i = tid; i < H_DIM * OUT_DIM; i += 256) {
        int k = i / OUT_DIM, c = i % OUT_DIM;
        Bs[k * 64 + c]      = Wmu[i];
        Bs[k * 64 + 32 + c] = Wlog[i];
    }
    __syncthreads();
    int row = blockIdx.x * 256 + tid;
    if (row >= n) return;

    ull acc[32];
#pragma unroll
    for (int i = 0; i < 32; i++) acc[i] = 0ull;

    const float4* arow = (const float4*)(g_h + (size_t)row * H_DIM);
#pragma unroll 2
    for (int k4 = 0; k4 < H_DIM / 4; k4++) {
        float4 a4 = arow[k4];
        a4.x = fmaxf(a4.x, 0.f);
        a4.y = fmaxf(a4.y, 0.f);
        a4.z = fmaxf(a4.z, 0.f);
        a4.w = fmaxf(a4.w, 0.f);
        float av[4] = {a4.x, a4.y, a4.z, a4.w};
#pragma unroll
        for (int kk = 0; kk < 4; kk++) {
            ull a2 = pack_dup(av[kk]);
            const ull* br = (const ull*)(Bs + (k4 * 4 + kk) * 64);
#pragma unroll
            for (int c = 0; c < 32; c++) FMA2(acc[c], a2, br[c]);
        }
    }
    longlong2* crow = (longlong2*)(g_Z2 + (size_t)row * H_DIM);
#pragma unroll
    for (int c = 0; c < 16; c++) {
        longlong2 v;
        v.x = (long long)acc[2 * c];
        v.y = (long long)acc[2 * c + 1];
        crow[c] = v;
    }
}

// ---------------- CSR aggregation 2: warp per node -> d_out ------------------
__global__ __launch_bounds__(256) void k_agg2_csr(const float* __restrict__ bmu,
                                                  const float* __restrict__ blog,
                                                  float* __restrict__ outMu,
                                                  float* __restrict__ outLog, int n) {
    int warp = (blockIdx.x * 256 + threadIdx.x) >> 5;
    int lane = threadIdx.x & 31;
    if (warp >= n) return;
    int half = lane >> 4, l16 = lane & 15;
    int rs = g_row[warp], re = g_row[warp + 1];
    const float4* zb = (const float4*)g_Z2;

    float4 acc;
    if (half == 0) {
        float dv = g_dinv[warp];
        float s2 = dv * dv;
        float4 zs = zb[(size_t)warp * 16 + l16];
        float4 b = (l16 < 8) ? ((const float4*)bmu)[l16]
                             : ((const float4*)blog)[l16 - 8];
        acc = make_float4(fmaf(zs.x, s2, b.x), fmaf(zs.y, s2, b.y),
                          fmaf(zs.z, s2, b.z), fmaf(zs.w, s2, b.w));
    } else {
        acc = make_float4(0.f, 0.f, 0.f, 0.f);
    }
    for (int e = rs + half; e < re; e += 2) {
        int2 ed = g_csr[e];
        float w = __int_as_float(ed.y);
        float4 z = zb[(size_t)ed.x * 16 + l16];
        acc.x = fmaf(w, z.x, acc.x);
        acc.y = fmaf(w, z.y, acc.y);
        acc.z = fmaf(w, z.z, acc.z);
        acc.w = fmaf(w, z.w, acc.w);
    }
    acc.x += __shfl_xor_sync(0xffffffffu, acc.x, 16);
    acc.y += __shfl_xor_sync(0xffffffffu, acc.y, 16);
    acc.z += __shfl_xor_sync(0xffffffffu, acc.z, 16);
    acc.w += __shfl_xor_sync(0xffffffffu, acc.w, 16);
    if (half == 0) {
        if (l16 < 8)
            ((float4*)(outMu + (size_t)warp * OUT_DIM))[l16] = acc;
        else
            ((float4*)(outLog + (size_t)warp * OUT_DIM))[l16 - 8] = acc;
    }
}

// ---------------- launch -----------------------------------------------------
extern "C" void kernel_launch(void* const* d_in, const int* in_sizes, int n_in,
                              void* d_out, int out_size) {
    const float* x    = (const float*)d_in[0];
    const int*   eraw = (const int*)d_in[1];
    const float* W1   = (const float*)d_in[2];
    const float* b1   = (const float*)d_in[3];
    const float* Wmu  = (const float*)d_in[4];
    const float* bmu  = (const float*)d_in[5];
    const float* Wlog = (const float*)d_in[6];
    const float* blog = (const float*)d_in[7];

    int N = in_sizes[0] / IN_DIM;   // 100000
    int E = in_sizes[1] / 2;        // 1600000
    if (N > MAXN) N = MAXN;
    if (E > MAXE) E = MAXE;

    float* outMu  = (float*)d_out;
    float* outLog = (float*)d_out + (size_t)N * OUT_DIM;

    const int T = 256;
    int gN   = (N + T - 1) / T;
    int gE   = (E + T - 1) / T;
    int gW   = (N * 32 + T - 1) / T;          // warp-per-node grids
    int nblk = (N + SCAN_B - 1) / SCAN_B;     // scan blocks (98)

    // Lazy side-stream + fork/join events (host objects only; created on the
    // first, uncaptured correctness call; reused verbatim inside the capture).
    static cudaStream_t s2 = nullptr;
    static cudaEvent_t  evFork = nullptr, evJoin = nullptr;
    if (s2 == nullptr) {
        cudaStreamCreateWithFlags(&s2, cudaStreamNonBlocking);
        cudaEventCreateWithFlags(&evFork, cudaEventDisableTiming);
        cudaEventCreateWithFlags(&evJoin, cudaEventDisableTiming);
    }

    // Fork: GEMM1 (x,W1 -> Z1) runs concurrently with the CSR build chain.
    cudaEventRecord(evFork, 0);
    cudaStreamWaitEvent(s2, evFork, 0);
    k_gemm1<<<gN, T, 0, s2>>>(x, W1, N);
    cudaEventRecord(evJoin, s2);

    // CSR build on the main stream (no staging; raw edge list read twice)
    k_zero<<<gN, T>>>(N);
    k_count<<<gE, T>>>(eraw, E, N);
    k_scanA<<<nblk, SCAN_B>>>(N);
    k_scanB<<<1, 128>>>(nblk, N);
    k_scanC<<<nblk, SCAN_B>>>(N);             // offsets + g_cur + dinv fused
    k_scatter<<<gE, T>>>(eraw, E, N);

    // Join: agg1 needs both Z1 (s2) and CSR (main stream)
    cudaStreamWaitEvent(0, evJoin, 0);

    // layer 1 aggregation
    k_agg1_csr<<<gW, T>>>(b1, N);

    // layer 2 (mu|log fused), aggregation writes d_out directly
    k_gemm2<<<gN, T>>>(Wmu, Wlog, N);
    k_agg2_csr<<<gW, T>>>(bmu, blog, outMu, outLog, N);
}

// round 13
// speedup vs baseline: 2.6446x; 1.1009x over previous
#include <cuda_runtime.h>
#include <cuda_fp16.h>

// Problem-fixed dims: N=100000, E=1600000, IN=128, H=64, OUT=32
#define MAXN 100000
#define MAXE 1600000
#define IN_DIM 128
#define H_DIM 64
#define OUT_DIM 32
#define SCAN_B 1024
#define MAX_BLK ((MAXN + SCAN_B - 1) / SCAN_B)   // 98

typedef unsigned long long ull;

// ---------------- scratch (device globals; no allocation allowed) ------------
__device__ __align__(16) int   g_cnt [MAXN];   // in-degree (excl self-loop)
__device__ __align__(16) int   g_row [MAXN + 1];
__device__ __align__(16) int   g_cur [MAXN];
__device__ __align__(16) int   g_bsum[MAX_BLK];
__device__ __align__(16) int   g_boff[MAX_BLK];
__device__ __align__(16) float g_dinv[MAXN];
__device__ __align__(16) int2  g_csr [MAXE];   // (src, norm-bits) grouped by dst
__device__ __align__(16) __half g_Z1h[(size_t)MAXN * H_DIM]; // x@W1      (fp16)
__device__ __align__(16) float  g_h [(size_t)MAXN * H_DIM];  // conv1 out (fp32)
__device__ __align__(16) __half g_Z2h[(size_t)MAXN * H_DIM]; // relu(h)@W (fp16)

// ---------------- bit-cast helpers (no intrinsic equivalents) ----------------
__device__ __forceinline__ unsigned h2u(__half2 h) {
    return *reinterpret_cast<unsigned*>(&h);
}
__device__ __forceinline__ __half2 u2h(unsigned u) {
    return *reinterpret_cast<__half2*>(&u);
}

// ---------------- f32x2 packed FMA helpers -----------------------------------
__device__ __forceinline__ ull pack_dup(float a) {
    ull r;
    asm("mov.b64 %0, {%1, %1};" : "=l"(r) : "r"(__float_as_uint(a)));
    return r;
}
#define FMA2(acc, a2, b2) \
    asm("fma.rn.f32x2 %0, %1, %2, %0;" : "+l"(acc) : "l"(a2), "l"(b2))

__device__ __forceinline__ float2 unpack2(ull v) {
    float2 f;
    asm("mov.b64 {%0, %1}, %2;" : "=f"(f.x), "=f"(f.y) : "l"(v));
    return f;
}

// ---------------- dtype probe helper (per-block, L2-hot, ~free) --------------
__device__ __forceinline__ int probe_is64(const int* __restrict__ raw, int E,
                                          int* sh_nz) {
    if (threadIdx.x == 0) *sh_nz = 0;
    __syncthreads();
    int K = 2048;
    if (K > 2 * E) K = 2 * E;
    int cnt = 0;
    for (int i = 2 * threadIdx.x + 1; i < K; i += 2 * blockDim.x)
        if (raw[i] != 0) cnt++;
    if (cnt) atomicAdd(sh_nz, cnt);
    __syncthreads();
    return (*sh_nz == 0);
}

// ---------------- zero counters ----------------------------------------------
__global__ void k_zero(int n) {
    int i = blockIdx.x * blockDim.x + threadIdx.x;
    if (i < n) g_cnt[i] = 0;
}

// ---------------- count in-degrees straight from raw edge list ---------------
__global__ __launch_bounds__(256) void k_count(const int* __restrict__ raw,
                                               int E, int n) {
    __shared__ int nz;
    int is64 = probe_is64(raw, E, &nz);
    int i = blockIdx.x * 256 + threadIdx.x;
    if (i >= E) return;
    int d = is64 ? (int)((const long long*)raw)[(size_t)E + i] : raw[E + i];
    if ((unsigned)d >= (unsigned)n) d = 0;
    atomicAdd(&g_cnt[d], 1);
}

// ---------------- hierarchical exclusive scan of g_cnt -----------------------
__global__ __launch_bounds__(SCAN_B) void k_scanA(int n) {
    __shared__ int sh[SCAN_B];
    int t = threadIdx.x;
    int i = blockIdx.x * SCAN_B + t;
    int v = (i < n) ? g_cnt[i] : 0;
    sh[t] = v;
    __syncthreads();
#pragma unroll
    for (int off = 1; off < SCAN_B; off <<= 1) {
        int u = (t >= off) ? sh[t - off] : 0;
        __syncthreads();
        sh[t] += u;
        __syncthreads();
    }
    if (i < n) g_row[i] = sh[t] - v;
    if (t == SCAN_B - 1) g_bsum[blockIdx.x] = sh[t];
}

__global__ __launch_bounds__(128) void k_scanB(int nblk, int n) {
    __shared__ int sh[128];
    int t = threadIdx.x;
    int v = (t < nblk) ? g_bsum[t] : 0;
    sh[t] = v;
    __syncthreads();
#pragma unroll
    for (int off = 1; off < 128; off <<= 1) {
        int u = (t >= off) ? sh[t - off] : 0;
        __syncthreads();
        sh[t] += u;
        __syncthreads();
    }
    if (t < nblk) g_boff[t] = sh[t] - v;
    if (t == 127) g_row[n] = sh[127];
}

// Phase C: add block offsets; mirror into g_cur; fused dinv.
__global__ __launch_bounds__(SCAN_B) void k_scanC(int n) {
    int i = blockIdx.x * SCAN_B + threadIdx.x;
    if (i < n) {
        int r = g_row[i] + g_boff[blockIdx.x];
        g_row[i] = r;
        g_cur[i] = r;
        g_dinv[i] = rsqrtf(1.0f + (float)g_cnt[i]);  // +1 self-loop
    }
}

// ---------------- scatter into CSR straight from raw (norm computed here) ----
__global__ __launch_bounds__(256) void k_scatter(const int* __restrict__ raw,
                                                 int E, int n) {
    __shared__ int nz;
    int is64 = probe_is64(raw, E, &nz);
    int i = blockIdx.x * 256 + threadIdx.x;
    if (i >= E) return;
    int s, d;
    if (is64) {
        const long long* e64 = (const long long*)raw;
        s = (int)e64[i];
        d = (int)e64[(size_t)E + i];
    } else {
        s = raw[i];
        d = raw[E + i];
    }
    if ((unsigned)s >= (unsigned)n) s = 0;
    if ((unsigned)d >= (unsigned)n) d = 0;
    float w = g_dinv[s] * g_dinv[d];
    int pos = atomicAdd(&g_cur[d], 1);
    g_csr[pos] = make_int2(s, __float_as_int(w));
}

// ---------------- GEMM1: Z1 = x @ W1, fp32 math, fp16 store ------------------
__global__ __launch_bounds__(256) void k_gemm1(const float* __restrict__ x,
                                               const float* __restrict__ W1, int n) {
    __shared__ __align__(16) float Bs[IN_DIM * H_DIM];  // 32 KB
    int tid = threadIdx.x;
    for (int i = tid; i < IN_DIM * H_DIM; i += 256) Bs[i] = W1[i];
    __syncthreads();
    int row = blockIdx.x * 256 + tid;
    if (row >= n) return;

    ull acc[32];   // 64 cols as 32 packed f32x2
#pragma unroll
    for (int i = 0; i < 32; i++) acc[i] = 0ull;

    const float4* arow = (const float4*)(x + (size_t)row * IN_DIM);
#pragma unroll 2
    for (int k4 = 0; k4 < IN_DIM / 4; k4++) {
        float4 a4 = arow[k4];
        float av[4] = {a4.x, a4.y, a4.z, a4.w};
#pragma unroll
        for (int kk = 0; kk < 4; kk++) {
            ull a2 = pack_dup(av[kk]);
            const ull* br = (const ull*)(Bs + (k4 * 4 + kk) * H_DIM);
#pragma unroll
            for (int c = 0; c < 32; c++) FMA2(acc[c], a2, br[c]);
        }
    }
    // convert to fp16: 32 half2 = 8 uint4 stores
    uint4* crow = (uint4*)(g_Z1h + (size_t)row * H_DIM);
#pragma unroll
    for (int q = 0; q < 8; q++) {
        uint4 v;
        float2 f0 = unpack2(acc[4 * q + 0]);
        float2 f1 = unpack2(acc[4 * q + 1]);
        float2 f2 = unpack2(acc[4 * q + 2]);
        float2 f3 = unpack2(acc[4 * q + 3]);
        v.x = h2u(__floats2half2_rn(f0.x, f0.y));
        v.y = h2u(__floats2half2_rn(f1.x, f1.y));
        v.z = h2u(__floats2half2_rn(f2.x, f2.y));
        v.w = h2u(__floats2half2_rn(f3.x, f3.y));
        crow[q] = v;
    }
}

// ---------------- CSR aggregation 1: warp/node, fp16 gather, fp32 acc --------
__global__ __launch_bounds__(256) void k_agg1_csr(const float* __restrict__ b1, int n) {
    int warp = (blockIdx.x * 256 + threadIdx.x) >> 5;
    int lane = threadIdx.x & 31;
    if (warp >= n) return;
    int half = lane >> 4, l16 = lane & 15;
    int rs = g_row[warp], re = g_row[warp + 1];
    const uint2* zb = (const uint2*)g_Z1h;   // uint2 = 4 halves = 4 cols

    float4 acc;
    if (half == 0) {   // seed self-loop + bias once
        float dv = g_dinv[warp];
        float s2 = dv * dv;
        uint2 z = zb[(size_t)warp * 16 + l16];
        float2 f0 = __half22float2(u2h(z.x));
        float2 f1 = __half22float2(u2h(z.y));
        float4 b  = ((const float4*)b1)[l16];
        acc = make_float4(fmaf(f0.x, s2, b.x), fmaf(f0.y, s2, b.y),
                          fmaf(f1.x, s2, b.z), fmaf(f1.y, s2, b.w));
    } else {
        acc = make_float4(0.f, 0.f, 0.f, 0.f);
    }
    for (int e = rs + half; e < re; e += 2) {
        int2 ed = g_csr[e];
        float w = __int_as_float(ed.y);
        uint2 z = zb[(size_t)ed.x * 16 + l16];
        float2 f0 = __half22float2(u2h(z.x));
        float2 f1 = __half22float2(u2h(z.y));
        acc.x = fmaf(w, f0.x, acc.x);
        acc.y = fmaf(w, f0.y, acc.y);
        acc.z = fmaf(w, f1.x, acc.z);
        acc.w = fmaf(w, f1.y, acc.w);
    }
    acc.x += __shfl_xor_sync(0xffffffffu, acc.x, 16);
    acc.y += __shfl_xor_sync(0xffffffffu, acc.y, 16);
    acc.z += __shfl_xor_sync(0xffffffffu, acc.z, 16);
    acc.w += __shfl_xor_sync(0xffffffffu, acc.w, 16);
    if (half == 0)
        ((float4*)g_h)[(size_t)warp * 16 + l16] = acc;
}

// ---------------- GEMM2: Z2 = relu(h) @ [Wmu|Wlog], fp16 store ---------------
__global__ __launch_bounds__(256) void k_gemm2(const float* __restrict__ Wmu,
                                               const float* __restrict__ Wlog, int n) {
    __shared__ __align__(16) float Bs[H_DIM * 64];  // cols 0..31 Wmu, 32..63 Wlog
    int tid = threadIdx.x;
    for (int i = tid; i < H_DIM * OUT_DIM; i += 256) {
        int k = i / OUT_DIM, c = i % OUT_DIM;
        Bs[k * 64 + c]      = Wmu[i];
        Bs[k * 64 + 32 + c] = Wlog[i];
    }
    __syncthreads();
    int row = blockIdx.x * 256 + tid;
    if (row >= n) return;

    ull acc[32];
#pragma unroll
    for (int i = 0; i < 32; i++) acc[i] = 0ull;

    const float4* arow = (const float4*)(g_h + (size_t)row * H_DIM);
#pragma unroll 2
    for (int k4 = 0; k4 < H_DIM / 4; k4++) {
        float4 a4 = arow[k4];
        a4.x = fmaxf(a4.x, 0.f);
        a4.y = fmaxf(a4.y, 0.f);
        a4.z = fmaxf(a4.z, 0.f);
        a4.w = fmaxf(a4.w, 0.f);
        float av[4] = {a4.x, a4.y, a4.z, a4.w};
#pragma unroll
        for (int kk = 0; kk < 4; kk++) {
            ull a2 = pack_dup(av[kk]);
            const ull* br = (const ull*)(Bs + (k4 * 4 + kk) * 64);
#pragma unroll
            for (int c = 0; c < 32; c++) FMA2(acc[c], a2, br[c]);
        }
    }
    uint4* crow = (uint4*)(g_Z2h + (size_t)row * H_DIM);
#pragma unroll
    for (int q = 0; q < 8; q++) {
        uint4 v;
        float2 f0 = unpack2(acc[4 * q + 0]);
        float2 f1 = unpack2(acc[4 * q + 1]);
        float2 f2 = unpack2(acc[4 * q + 2]);
        float2 f3 = unpack2(acc[4 * q + 3]);
        v.x = h2u(__floats2half2_rn(f0.x, f0.y));
        v.y = h2u(__floats2half2_rn(f1.x, f1.y));
        v.z = h2u(__floats2half2_rn(f2.x, f2.y));
        v.w = h2u(__floats2half2_rn(f3.x, f3.y));
        crow[q] = v;
    }
}

// ---------------- CSR aggregation 2: warp/node, fp16 gather -> d_out ---------
__global__ __launch_bounds__(256) void k_agg2_csr(const float* __restrict__ bmu,
                                                  const float* __restrict__ blog,
                                                  float* __restrict__ outMu,
                                                  float* __restrict__ outLog, int n) {
    int warp = (blockIdx.x * 256 + threadIdx.x) >> 5;
    int lane = threadIdx.x & 31;
    if (warp >= n) return;
    int half = lane >> 4, l16 = lane & 15;
    int rs = g_row[warp], re = g_row[warp + 1];
    const uint2* zb = (const uint2*)g_Z2h;

    float4 acc;
    if (half == 0) {
        float dv = g_dinv[warp];
        float s2 = dv * dv;
        uint2 z = zb[(size_t)warp * 16 + l16];
        float2 f0 = __half22float2(u2h(z.x));
        float2 f1 = __half22float2(u2h(z.y));
        float4 b = (l16 < 8) ? ((const float4*)bmu)[l16]
                             : ((const float4*)blog)[l16 - 8];
        acc = make_float4(fmaf(f0.x, s2, b.x), fmaf(f0.y, s2, b.y),
                          fmaf(f1.x, s2, b.z), fmaf(f1.y, s2, b.w));
    } else {
        acc = make_float4(0.f, 0.f, 0.f, 0.f);
    }
    for (int e = rs + half; e < re; e += 2) {
        int2 ed = g_csr[e];
        float w = __int_as_float(ed.y);
        uint2 z = zb[(size_t)ed.x * 16 + l16];
        float2 f0 = __half22float2(u2h(z.x));
        float2 f1 = __half22float2(u2h(z.y));
        acc.x = fmaf(w, f0.x, acc.x);
        acc.y = fmaf(w, f0.y, acc.y);
        acc.z = fmaf(w, f1.x, acc.z);
        acc.w = fmaf(w, f1.y, acc.w);
    }
    acc.x += __shfl_xor_sync(0xffffffffu, acc.x, 16);
    acc.y += __shfl_xor_sync(0xffffffffu, acc.y, 16);
    acc.z += __shfl_xor_sync(0xffffffffu, acc.z, 16);
    acc.w += __shfl_xor_sync(0xffffffffu, acc.w, 16);
    if (half == 0) {
        if (l16 < 8)
            ((float4*)(outMu + (size_t)warp * OUT_DIM))[l16] = acc;
        else
            ((float4*)(outLog + (size_t)warp * OUT_DIM))[l16 - 8] = acc;
    }
}

// ---------------- launch -----------------------------------------------------
extern "C" void kernel_launch(void* const* d_in, const int* in_sizes, int n_in,
                              void* d_out, int out_size) {
    const float* x    = (const float*)d_in[0];
    const int*   eraw = (const int*)d_in[1];
    const float* W1   = (const float*)d_in[2];
    const float* b1   = (const float*)d_in[3];
    const float* Wmu  = (const float*)d_in[4];
    const float* bmu  = (const float*)d_in[5];
    const float* Wlog = (const float*)d_in[6];
    const float* blog = (const float*)d_in[7];

    int N = in_sizes[0] / IN_DIM;   // 100000
    int E = in_sizes[1] / 2;        // 1600000
    if (N > MAXN) N = MAXN;
    if (E > MAXE) E = MAXE;

    float* outMu  = (float*)d_out;
    float* outLog = (float*)d_out + (size_t)N * OUT_DIM;

    const int T = 256;
    int gN   = (N + T - 1) / T;
    int gE   = (E + T - 1) / T;
    int gW   = (N * 32 + T - 1) / T;          // warp-per-node grids
    int nblk = (N + SCAN_B - 1) / SCAN_B;     // scan blocks (98)

    // Lazy side-stream + fork/join events (host objects only).
    static cudaStream_t s2 = nullptr;
    static cudaEvent_t  evFork = nullptr, evJoin = nullptr;
    if (s2 == nullptr) {
        cudaStreamCreateWithFlags(&s2, cudaStreamNonBlocking);
        cudaEventCreateWithFlags(&evFork, cudaEventDisableTiming);
        cudaEventCreateWithFlags(&evJoin, cudaEventDisableTiming);
    }

    // Fork: GEMM1 runs concurrently with the CSR build chain.
    cudaEventRecord(evFork, 0);
    cudaStreamWaitEvent(s2, evFork, 0);
    k_gemm1<<<gN, T, 0, s2>>>(x, W1, N);
    cudaEventRecord(evJoin, s2);

    // CSR build on the main stream
    k_zero<<<gN, T>>>(N);
    k_count<<<gE, T>>>(eraw, E, N);
    k_scanA<<<nblk, SCAN_B>>>(N);
    k_scanB<<<1, 128>>>(nblk, N);
    k_scanC<<<nblk, SCAN_B>>>(N);             // offsets + g_cur + dinv fused
    k_scatter<<<gE, T>>>(eraw, E, N);

    // Join: agg1 needs both Z1 (s2) and CSR (main stream)
    cudaStreamWaitEvent(0, evJoin, 0);

    // layer 1 aggregation
    k_agg1_csr<<<gW, T>>>(b1, N);

    // layer 2 (mu|log fused), aggregation writes d_out directly
    k_gemm2<<<gN, T>>>(Wmu, Wlog, N);
    k_agg2_csr<<<gW, T>>>(bmu, blog, outMu, outLog, N);
}